// round 1
// baseline (speedup 1.0000x reference)
#include <cuda_runtime.h>
#include <math.h>

#define BB 4
#define CIN 128
#define TQ 256
#define TS 257
#define TD 65
#define HID 256
#define COUT 512
#define NHEAD 8
#define EDIM 32

// ---------------- scratch (static device globals; no allocation) ----------------
__device__ float g_pooled[BB*CIN*TQ*TD];     // pooled corr tokens [4,128,256,65]
__device__ float g_k[BB*HID*TQ*TS];          // K [4,256,256,257]
__device__ float g_v[BB*HID*TQ*TS];          // V
__device__ float g_q[BB*HID*TQ*TD];          // Q (pooled) [4,256,256,65]
__device__ float g_res[BB*COUT*TQ*TD];       // residual path [4,512,256,65]
__device__ float g_att[BB*HID*TQ*TD];        // attention output [4,256,256,65]
__device__ float g_agg[BB*COUT*TQ*TD];       // agg conv output [4,512,256,65]
__device__ float g_mask[BB*256];
__device__ float g_partial[16*128*2];
__device__ float g_stats[16*2];

// ---------------- cst_pool on corr tokens ----------------
__global__ void pool_kernel(const float* __restrict__ in, float* __restrict__ out) {
    int idx = blockIdx.x*blockDim.x + threadIdx.x;
    const int n = BB*CIN*TQ*TD;
    if (idx >= n) return;
    int sp = idx % TD;
    int q  = (idx/TD) % TQ;
    int c  = (idx/(TD*TQ)) % CIN;
    int b  = idx/(TD*TQ*CIN);
    const float* src = in + ((long)(b*CIN + c)*TQ + q)*TS;
    float v;
    if (sp == 0) {
        v = src[0];
    } else {
        int t = sp - 1;
        int i = t >> 3, j = t & 7;
        const float* p = src + 1 + (i*2)*16 + j*2;
        v = 0.25f*(p[0] + p[1] + p[16] + p[17]);
    }
    out[idx] = v;
}

// ---------------- mask: exact bilinear subsample ----------------
__global__ void mask_kernel(const int* __restrict__ s, float* __restrict__ m) {
    int idx = blockIdx.x*blockDim.x + threadIdx.x;
    if (idx >= BB*256) return;
    int b = idx >> 8;
    int r = idx & 255;
    int i = r >> 4, j = r & 15;
    int v = s[b*65536 + (i*17)*256 + j*17];
    m[idx] = (v > 0) ? 1.0f : 0.0f;
}

// ---------------- generic batched GEMM: Y[b] = W @ X[b] (+ bias) ----------------
// W: [M,K] row-major, X: [B,K,N], Y: [B,M,N]. Grid: (N/64, M/64, B), 256 threads.
__global__ void gemm_kernel(const float* __restrict__ W, const float* __restrict__ bias,
                            const float* __restrict__ X, float* __restrict__ Y,
                            int M, int N, int K) {
    __shared__ float As[16][68];   // padded for bank-friendly, float4-aligned reads
    __shared__ float Bs[16][64];
    int b  = blockIdx.z;
    const float* Xb = X + (long)b*K*N;
    float* Yb = Y + (long)b*M*N;
    int n0 = blockIdx.x*64, m0 = blockIdx.y*64;
    int tid = threadIdx.x;
    int tx = tid & 15, ty = tid >> 4;

    float acc[4][4];
    #pragma unroll
    for (int i = 0; i < 4; i++)
        #pragma unroll
        for (int j = 0; j < 4; j++) acc[i][j] = 0.f;

    for (int k0 = 0; k0 < K; k0 += 16) {
        #pragma unroll
        for (int i = 0; i < 4; i++) {
            int idx = tid + i*256;
            int kk = idx & 15, mm = idx >> 4;       // coalesced-ish along k (W is L2-resident)
            As[kk][mm] = W[(long)(m0+mm)*K + k0 + kk];
        }
        #pragma unroll
        for (int i = 0; i < 4; i++) {
            int idx = tid + i*256;
            int nn = idx & 63, kk = idx >> 6;        // fully coalesced
            Bs[kk][nn] = Xb[(long)(k0+kk)*N + n0 + nn];
        }
        __syncthreads();
        #pragma unroll
        for (int k = 0; k < 16; k++) {
            float4 a = *(const float4*)&As[k][ty*4];
            float4 bv = *(const float4*)&Bs[k][tx*4];
            acc[0][0] += a.x*bv.x; acc[0][1] += a.x*bv.y; acc[0][2] += a.x*bv.z; acc[0][3] += a.x*bv.w;
            acc[1][0] += a.y*bv.x; acc[1][1] += a.y*bv.y; acc[1][2] += a.y*bv.z; acc[1][3] += a.y*bv.w;
            acc[2][0] += a.z*bv.x; acc[2][1] += a.z*bv.y; acc[2][2] += a.z*bv.z; acc[2][3] += a.z*bv.w;
            acc[3][0] += a.w*bv.x; acc[3][1] += a.w*bv.y; acc[3][2] += a.w*bv.z; acc[3][3] += a.w*bv.w;
        }
        __syncthreads();
    }
    #pragma unroll
    for (int i = 0; i < 4; i++) {
        int mrow = m0 + ty*4 + i;
        float bs = bias ? bias[mrow] : 0.f;
        #pragma unroll
        for (int j = 0; j < 4; j++) {
            Yb[(long)mrow*N + n0 + tx*4 + j] = acc[i][j] + bs;
        }
    }
}

// ---------------- GroupNorm: 2-stage deterministic reduce + apply ----------------
__global__ void gn_reduce(const float* __restrict__ x, const float* __restrict__ y,
                          float* __restrict__ partial, long groupSize) {
    long bg = blockIdx.y;
    long base = bg*groupSize;
    int tid = threadIdx.x;
    float s1 = 0.f, s2 = 0.f;
    for (long i = (long)blockIdx.x*blockDim.x + tid; i < groupSize; i += (long)gridDim.x*blockDim.x) {
        float v = x[base + i];
        if (y) v += y[base + i];
        s1 += v; s2 += v*v;
    }
    __shared__ float sh1[256], sh2[256];
    sh1[tid] = s1; sh2[tid] = s2;
    __syncthreads();
    for (int o = 128; o > 0; o >>= 1) {
        if (tid < o) { sh1[tid] += sh1[tid+o]; sh2[tid] += sh2[tid+o]; }
        __syncthreads();
    }
    if (tid == 0) {
        partial[(bg*gridDim.x + blockIdx.x)*2 + 0] = sh1[0];
        partial[(bg*gridDim.x + blockIdx.x)*2 + 1] = sh2[0];
    }
}

__global__ void gn_finalize(const float* __restrict__ partial, float* __restrict__ stats,
                            int nb, float invN) {
    int bg = threadIdx.x;
    if (bg >= 16) return;
    float s1 = 0.f, s2 = 0.f;
    for (int i = 0; i < nb; i++) {
        s1 += partial[(bg*nb + i)*2 + 0];
        s2 += partial[(bg*nb + i)*2 + 1];
    }
    float mean = s1*invN;
    float var  = fmaxf(s2*invN - mean*mean, 0.f);
    stats[bg*2 + 0] = mean;
    stats[bg*2 + 1] = 1.0f/sqrtf(var + 1e-5f);
}

__global__ void gn_apply(const float* __restrict__ x, const float* __restrict__ y,
                         float* __restrict__ out,
                         const float* __restrict__ w, const float* __restrict__ bvec,
                         const float* __restrict__ stats,
                         long groupSize, int T, int C, long n, int doRelu) {
    long idx = (long)blockIdx.x*blockDim.x + threadIdx.x;
    if (idx >= n) return;
    int bg = (int)(idx / groupSize);
    int c  = (int)((idx / T) % C);
    float v = x[idx];
    if (y) v += y[idx];
    v = (v - stats[bg*2])*stats[bg*2 + 1]*w[c] + bvec[c];
    if (doRelu) v = fmaxf(v, 0.f);
    out[idx] = v;
}

// ---------------- fused attention: S=Q^T K, mask, softmax, O = A V^T ----------------
// Grid: (Tq, NHEAD, B), 256 threads, dynamic smem.
#define SM_Q   (32*68)
#define SM_K   (32*260)
#define SM_S   (68*260)
#define SMEM_FLOATS (SM_Q + 2*SM_K + SM_S + 256)
#define SMEM_BYTES  (SMEM_FLOATS*4)

__global__ void attn_kernel(const float* __restrict__ gq, const float* __restrict__ gk,
                            const float* __restrict__ gv, const float* __restrict__ gm,
                            float* __restrict__ gout) {
    extern __shared__ float sm[];
    float* Qs = sm;                  // [32][68]  (d padded 65->68, pad=0)
    float* Ks = Qs + SM_Q;           // [32][260] (s padded 257->260, pad=0)
    float* Vs = Ks + SM_K;           // [32][260]
    float* S  = Vs + SM_K;           // [68][260]
    float* Ms = S  + SM_S;           // [256]

    int q = blockIdx.x, g = blockIdx.y, b = blockIdx.z;
    int tid = threadIdx.x;
    long qbase = ((long)(b*HID + g*EDIM)*TQ + q)*TD;
    long kbase = ((long)(b*HID + g*EDIM)*TQ + q)*TS;

    for (int i = tid; i < SM_Q; i += 256) {
        int e = i/68, d = i%68;
        Qs[i] = (d < TD) ? gq[qbase + (long)e*TQ*TD + d] : 0.f;
    }
    for (int i = tid; i < SM_K; i += 256) {
        int e = i/260, s = i%260;
        float kv = 0.f, vv = 0.f;
        if (s < TS) { long off = kbase + (long)e*TQ*TS + s; kv = gk[off]; vv = gv[off]; }
        Ks[i] = kv; Vs[i] = vv;
    }
    if (tid < 256) Ms[tid] = gm[b*256 + tid];
    __syncthreads();

    // S[d][s] = sum_e Q[e][d]*K[e][s], 4x4 register tiles over padded 68x260
    for (int t = tid; t < 17*65; t += 256) {
        int dt = t/65, st = t%65;
        float acc[4][4];
        #pragma unroll
        for (int i = 0; i < 4; i++)
            #pragma unroll
            for (int j = 0; j < 4; j++) acc[i][j] = 0.f;
        #pragma unroll
        for (int e = 0; e < 32; e++) {
            float4 a = *(const float4*)&Qs[e*68 + dt*4];
            float4 k4 = *(const float4*)&Ks[e*260 + st*4];
            acc[0][0] += a.x*k4.x; acc[0][1] += a.x*k4.y; acc[0][2] += a.x*k4.z; acc[0][3] += a.x*k4.w;
            acc[1][0] += a.y*k4.x; acc[1][1] += a.y*k4.y; acc[1][2] += a.y*k4.z; acc[1][3] += a.y*k4.w;
            acc[2][0] += a.z*k4.x; acc[2][1] += a.z*k4.y; acc[2][2] += a.z*k4.z; acc[2][3] += a.z*k4.w;
            acc[3][0] += a.w*k4.x; acc[3][1] += a.w*k4.y; acc[3][2] += a.w*k4.z; acc[3][3] += a.w*k4.w;
        }
        #pragma unroll
        for (int i = 0; i < 4; i++)
            #pragma unroll
            for (int j = 0; j < 4; j++) {
                int s = st*4 + j;
                float v = acc[i][j];
                if (s >= 1 && s < TS && Ms[s-1] == 0.f) v = -1e9f;
                S[(dt*4 + i)*260 + s] = v;
            }
    }
    __syncthreads();

    // row softmax over s<257 (one warp per row), zero the 3 pad columns
    int wid = tid >> 5, lane = tid & 31;
    for (int d = wid; d < TD; d += 8) {
        float mx = -1e30f;
        for (int s = lane; s < TS; s += 32) mx = fmaxf(mx, S[d*260 + s]);
        #pragma unroll
        for (int o = 16; o > 0; o >>= 1) mx = fmaxf(mx, __shfl_xor_sync(0xffffffffu, mx, o));
        float sum = 0.f;
        for (int s = lane; s < TS; s += 32) {
            float e = expf(S[d*260 + s] - mx);
            S[d*260 + s] = e;
            sum += e;
        }
        #pragma unroll
        for (int o = 16; o > 0; o >>= 1) sum += __shfl_xor_sync(0xffffffffu, sum, o);
        float inv = 1.0f/sum;
        for (int s = lane; s < TS; s += 32) S[d*260 + s] *= inv;
        if (lane < 3) S[d*260 + TS + lane] = 0.f;
    }
    __syncthreads();

    // O[e][d] = sum_s A[d][s]*V[e][s]; 4e x 4d tiles, float4 over s
    long obase = qbase;
    for (int t = tid; t < 8*17; t += 256) {
        int et = t/17, dt = t%17;
        float acc[4][4];    // [e][d]
        #pragma unroll
        for (int j = 0; j < 4; j++)
            #pragma unroll
            for (int i = 0; i < 4; i++) acc[j][i] = 0.f;
        for (int s4 = 0; s4 < 65; s4++) {
            float4 a0 = *(const float4*)&S[(dt*4 + 0)*260 + s4*4];
            float4 a1 = *(const float4*)&S[(dt*4 + 1)*260 + s4*4];
            float4 a2 = *(const float4*)&S[(dt*4 + 2)*260 + s4*4];
            float4 a3 = *(const float4*)&S[(dt*4 + 3)*260 + s4*4];
            float4 v0 = *(const float4*)&Vs[(et*4 + 0)*260 + s4*4];
            float4 v1 = *(const float4*)&Vs[(et*4 + 1)*260 + s4*4];
            float4 v2 = *(const float4*)&Vs[(et*4 + 2)*260 + s4*4];
            float4 v3 = *(const float4*)&Vs[(et*4 + 3)*260 + s4*4];
            acc[0][0] += a0.x*v0.x + a0.y*v0.y + a0.z*v0.z + a0.w*v0.w;
            acc[0][1] += a1.x*v0.x + a1.y*v0.y + a1.z*v0.z + a1.w*v0.w;
            acc[0][2] += a2.x*v0.x + a2.y*v0.y + a2.z*v0.z + a2.w*v0.w;
            acc[0][3] += a3.x*v0.x + a3.y*v0.y + a3.z*v0.z + a3.w*v0.w;
            acc[1][0] += a0.x*v1.x + a0.y*v1.y + a0.z*v1.z + a0.w*v1.w;
            acc[1][1] += a1.x*v1.x + a1.y*v1.y + a1.z*v1.z + a1.w*v1.w;
            acc[1][2] += a2.x*v1.x + a2.y*v1.y + a2.z*v1.z + a2.w*v1.w;
            acc[1][3] += a3.x*v1.x + a3.y*v1.y + a3.z*v1.z + a3.w*v1.w;
            acc[2][0] += a0.x*v2.x + a0.y*v2.y + a0.z*v2.z + a0.w*v2.w;
            acc[2][1] += a1.x*v2.x + a1.y*v2.y + a1.z*v2.z + a1.w*v2.w;
            acc[2][2] += a2.x*v2.x + a2.y*v2.y + a2.z*v2.z + a2.w*v2.w;
            acc[2][3] += a3.x*v2.x + a3.y*v2.y + a3.z*v2.z + a3.w*v2.w;
            acc[3][0] += a0.x*v3.x + a0.y*v3.y + a0.z*v3.z + a0.w*v3.w;
            acc[3][1] += a1.x*v3.x + a1.y*v3.y + a1.z*v3.z + a1.w*v3.w;
            acc[3][2] += a2.x*v3.x + a2.y*v3.y + a2.z*v3.z + a2.w*v3.w;
            acc[3][3] += a3.x*v3.x + a3.y*v3.y + a3.z*v3.z + a3.w*v3.w;
        }
        #pragma unroll
        for (int j = 0; j < 4; j++)
            #pragma unroll
            for (int i = 0; i < 4; i++) {
                int d = dt*4 + i;
                if (d < TD)
                    gout[obase + (long)(et*4 + j)*TQ*TD + d] = acc[j][i];
            }
    }
}

// ---------------- host orchestration ----------------
static void run_gn(const float* x, const float* y, float* out,
                   const float* w, const float* bvec,
                   float* partial, float* stats,
                   int C, int T, int doRelu) {
    long groupSize = (long)(C/4)*T;
    long n = (long)BB*C*T;
    float invN = 1.0f/(float)groupSize;
    gn_reduce<<<dim3(128, 16), 256>>>(x, y, partial, groupSize);
    gn_finalize<<<1, 16>>>(partial, stats, 128, invN);
    gn_apply<<<(unsigned)((n + 255)/256), 256>>>(x, y, out, w, bvec, stats, groupSize, T, C, n, doRelu);
}

extern "C" void kernel_launch(void* const* d_in, const int* in_sizes, int n_in,
                              void* d_out, int out_size) {
    const float* corr   = (const float*)d_in[0];
    const int*   smask  = (const int*)  d_in[1];
    const float* W_sc   = (const float*)d_in[2];
    const float* gnscw  = (const float*)d_in[3];
    const float* gnscb  = (const float*)d_in[4];
    const float* W_qkv  = (const float*)d_in[5];
    const float* b_qkv  = (const float*)d_in[6];
    const float* gn1w   = (const float*)d_in[7];
    const float* gn1b   = (const float*)d_in[8];
    const float* W_agg  = (const float*)d_in[9];
    const float* gn2w   = (const float*)d_in[10];
    const float* gn2b   = (const float*)d_in[11];
    const float* gnow   = (const float*)d_in[12];
    const float* gnob   = (const float*)d_in[13];
    float* out = (float*)d_out;

    float *pooled, *k, *v, *q, *res, *att, *agg, *mask, *partial, *stats;
    cudaGetSymbolAddress((void**)&pooled, g_pooled);
    cudaGetSymbolAddress((void**)&k,      g_k);
    cudaGetSymbolAddress((void**)&v,      g_v);
    cudaGetSymbolAddress((void**)&q,      g_q);
    cudaGetSymbolAddress((void**)&res,    g_res);
    cudaGetSymbolAddress((void**)&att,    g_att);
    cudaGetSymbolAddress((void**)&agg,    g_agg);
    cudaGetSymbolAddress((void**)&mask,   g_mask);
    cudaGetSymbolAddress((void**)&partial,g_partial);
    cudaGetSymbolAddress((void**)&stats,  g_stats);

    const int NPOOL = TQ*TD;     // 16640
    const int NFULL = TQ*TS;     // 65792

    // 1. pooled corr + mask
    pool_kernel<<<(BB*CIN*TQ*TD + 255)/256, 256>>>(corr, pooled);
    mask_kernel<<<4, 256>>>(smask, mask);

    // 2. GEMMs: Q (on pooled, +bias), residual-pre (on pooled), K and V (on full corr, +bias)
    gemm_kernel<<<dim3(NPOOL/64, HID/64,  BB), 256>>>(W_qkv,              b_qkv,       pooled, q,   HID,  NPOOL, CIN);
    gemm_kernel<<<dim3(NPOOL/64, COUT/64, BB), 256>>>(W_sc,               nullptr,     pooled, res, COUT, NPOOL, CIN);
    gemm_kernel<<<dim3(NFULL/64, HID/64,  BB), 256>>>(W_qkv + 256*CIN,    b_qkv + 256, corr,   k,   HID,  NFULL, CIN);
    gemm_kernel<<<dim3(NFULL/64, HID/64,  BB), 256>>>(W_qkv + 512*CIN,    b_qkv + 512, corr,   v,   HID,  NFULL, CIN);

    // 3. residual = relu(gn_sc(res))
    run_gn(res, nullptr, res, gnscw, gnscb, partial, stats, COUT, NPOOL, 1);

    // 4. attention
    cudaFuncSetAttribute(attn_kernel, cudaFuncAttributeMaxDynamicSharedMemorySize, SMEM_BYTES);
    attn_kernel<<<dim3(TQ, NHEAD, BB), 256, SMEM_BYTES>>>(q, k, v, mask, att);

    // 5. out = relu(gn1(att))
    run_gn(att, nullptr, att, gn1w, gn1b, partial, stats, HID, NPOOL, 1);

    // 6. agg = W_agg @ att
    gemm_kernel<<<dim3(NPOOL/64, COUT/64, BB), 256>>>(W_agg, nullptr, att, agg, COUT, NPOOL, HID);

    // 7. agg = relu(gn2(agg))
    run_gn(agg, nullptr, agg, gn2w, gn2b, partial, stats, COUT, NPOOL, 1);

    // 8. out = gn_out(agg + res)
    run_gn(agg, res, out, gnow, gnob, partial, stats, COUT, NPOOL, 0);
}

// round 2
// speedup vs baseline: 1.4337x; 1.4337x over previous
#include <cuda_runtime.h>
#include <math.h>

#define BB 4
#define CIN 128
#define TQ 256
#define TS 257
#define TD 65
#define HID 256
#define COUT 512
#define NHEAD 8
#define EDIM 32

// ---------------- scratch (static device globals; no allocation) ----------------
__device__ float g_pooled[BB*CIN*TQ*TD];     // pooled corr tokens [4,128,256,65]
__device__ float g_kv[BB*2*HID*TQ*TS];       // K (ch 0..255) and V (ch 256..511), [4,512,256,257]
__device__ float g_q[BB*HID*TQ*TD];          // Q (pooled) [4,256,256,65]
__device__ float g_res[BB*COUT*TQ*TD];       // residual path [4,512,256,65]
__device__ float g_att[BB*HID*TQ*TD];        // attention output [4,256,256,65]
__device__ float g_agg[BB*COUT*TQ*TD];       // agg conv output [4,512,256,65]
__device__ float g_mask[BB*256];
__device__ float g_partial[16*128*2];
__device__ float g_stats[16*2];

// ---------------- cst_pool on corr tokens ----------------
__global__ void pool_kernel(const float* __restrict__ in, float* __restrict__ out) {
    int idx = blockIdx.x*blockDim.x + threadIdx.x;
    const int n = BB*CIN*TQ*TD;
    if (idx >= n) return;
    int sp = idx % TD;
    int q  = (idx/TD) % TQ;
    int c  = (idx/(TD*TQ)) % CIN;
    int b  = idx/(TD*TQ*CIN);
    const float* src = in + ((long)(b*CIN + c)*TQ + q)*TS;
    float v;
    if (sp == 0) {
        v = src[0];
    } else {
        int t = sp - 1;
        int i = t >> 3, j = t & 7;
        const float* p = src + 1 + (i*2)*16 + j*2;
        v = 0.25f*(p[0] + p[1] + p[16] + p[17]);
    }
    out[idx] = v;
}

// ---------------- mask: exact bilinear subsample ----------------
__global__ void mask_kernel(const int* __restrict__ s, float* __restrict__ m) {
    int idx = blockIdx.x*blockDim.x + threadIdx.x;
    if (idx >= BB*256) return;
    int b = idx >> 8;
    int r = idx & 255;
    int i = r >> 4, j = r & 15;
    int v = s[b*65536 + (i*17)*256 + j*17];
    m[idx] = (v > 0) ? 1.0f : 0.0f;
}

// ---------------- 128x128x8 double-buffered GEMM: Y[b] = W @ X[b] (+bias) ----------------
// W: [M,K] row-major, X: [B,K,N], Y: [B,M,N].
// Grid: (N/128, M/128, B), 256 threads, 8x8 per thread.
__global__ void __launch_bounds__(256, 2)
gemm128(const float* __restrict__ W, const float* __restrict__ bias,
        const float* __restrict__ X, float* __restrict__ Y,
        int M, int N, int K) {
    __shared__ float As[2][8][132];   // padded row (132) => conflict-free STS, 16B-aligned rows
    __shared__ float Bs[2][8][128];

    int b  = blockIdx.z;
    const float* Xb = X + (long)b*K*N;
    float* Yb = Y + (long)b*M*N;
    int n0 = blockIdx.x*128, m0 = blockIdx.y*128;
    int tid = threadIdx.x;
    int tx = tid & 15, ty = tid >> 4;

    // A-tile load map: 128 rows x 8 k, one float4 per thread
    int arow = tid >> 1, acol = (tid & 1)*4;
    // B-tile load map: 8 k-rows x 128 n, one float4 per thread (coalesced)
    int brow = tid >> 5, bcol = (tid & 31)*4;

    const float* Aptr = W  + (long)(m0 + arow)*K + acol;
    const float* Bptr = Xb + (long)brow*N + n0 + bcol;

    float4 ra = *(const float4*)Aptr;
    float4 rb = *(const float4*)Bptr;
    As[0][acol+0][arow] = ra.x;
    As[0][acol+1][arow] = ra.y;
    As[0][acol+2][arow] = ra.z;
    As[0][acol+3][arow] = ra.w;
    *(float4*)&Bs[0][brow][bcol] = rb;
    __syncthreads();

    float acc[8][8];
    #pragma unroll
    for (int i = 0; i < 8; i++)
        #pragma unroll
        for (int j = 0; j < 8; j++) acc[i][j] = 0.f;

    int nt = K >> 3;
    for (int t = 0; t < nt; t++) {
        int cur = t & 1;
        if (t + 1 < nt) {
            ra = *(const float4*)(Aptr + (t+1)*8);
            rb = *(const float4*)(Bptr + (long)(t+1)*8*N);
        }
        #pragma unroll
        for (int kk = 0; kk < 8; kk++) {
            float4 a0 = *(const float4*)&As[cur][kk][ty*4];
            float4 a1 = *(const float4*)&As[cur][kk][ty*4 + 64];
            float4 b0 = *(const float4*)&Bs[cur][kk][tx*4];
            float4 b1 = *(const float4*)&Bs[cur][kk][tx*4 + 64];
            float av[8] = {a0.x,a0.y,a0.z,a0.w,a1.x,a1.y,a1.z,a1.w};
            float bv[8] = {b0.x,b0.y,b0.z,b0.w,b1.x,b1.y,b1.z,b1.w};
            #pragma unroll
            for (int i = 0; i < 8; i++)
                #pragma unroll
                for (int j = 0; j < 8; j++)
                    acc[i][j] += av[i]*bv[j];
        }
        if (t + 1 < nt) {
            int nxt = cur ^ 1;
            As[nxt][acol+0][arow] = ra.x;
            As[nxt][acol+1][arow] = ra.y;
            As[nxt][acol+2][arow] = ra.z;
            As[nxt][acol+3][arow] = ra.w;
            *(float4*)&Bs[nxt][brow][bcol] = rb;
            __syncthreads();
        }
    }

    #pragma unroll
    for (int ih = 0; ih < 2; ih++)
        #pragma unroll
        for (int i = 0; i < 4; i++) {
            int r = ih*4 + i;
            int mrow = m0 + ih*64 + ty*4 + i;
            float bs = bias ? bias[mrow] : 0.f;
            float4 o0 = make_float4(acc[r][0]+bs, acc[r][1]+bs, acc[r][2]+bs, acc[r][3]+bs);
            float4 o1 = make_float4(acc[r][4]+bs, acc[r][5]+bs, acc[r][6]+bs, acc[r][7]+bs);
            *(float4*)&Yb[(long)mrow*N + n0 + tx*4]      = o0;
            *(float4*)&Yb[(long)mrow*N + n0 + 64 + tx*4] = o1;
        }
}

// ---------------- GroupNorm: 2-stage deterministic reduce + apply ----------------
__global__ void gn_reduce(const float* __restrict__ x, const float* __restrict__ y,
                          float* __restrict__ partial, long groupSize) {
    long bg = blockIdx.y;
    long base = bg*groupSize;
    int tid = threadIdx.x;
    float s1 = 0.f, s2 = 0.f;
    for (long i = (long)blockIdx.x*blockDim.x + tid; i < groupSize; i += (long)gridDim.x*blockDim.x) {
        float v = x[base + i];
        if (y) v += y[base + i];
        s1 += v; s2 += v*v;
    }
    __shared__ float sh1[256], sh2[256];
    sh1[tid] = s1; sh2[tid] = s2;
    __syncthreads();
    for (int o = 128; o > 0; o >>= 1) {
        if (tid < o) { sh1[tid] += sh1[tid+o]; sh2[tid] += sh2[tid+o]; }
        __syncthreads();
    }
    if (tid == 0) {
        partial[(bg*gridDim.x + blockIdx.x)*2 + 0] = sh1[0];
        partial[(bg*gridDim.x + blockIdx.x)*2 + 1] = sh2[0];
    }
}

__global__ void gn_finalize(const float* __restrict__ partial, float* __restrict__ stats,
                            int nb, float invN) {
    int bg = threadIdx.x;
    if (bg >= 16) return;
    float s1 = 0.f, s2 = 0.f;
    for (int i = 0; i < nb; i++) {
        s1 += partial[(bg*nb + i)*2 + 0];
        s2 += partial[(bg*nb + i)*2 + 1];
    }
    float mean = s1*invN;
    float var  = fmaxf(s2*invN - mean*mean, 0.f);
    stats[bg*2 + 0] = mean;
    stats[bg*2 + 1] = 1.0f/sqrtf(var + 1e-5f);
}

__global__ void gn_apply(const float* __restrict__ x, const float* __restrict__ y,
                         float* __restrict__ out,
                         const float* __restrict__ w, const float* __restrict__ bvec,
                         const float* __restrict__ stats,
                         long groupSize, int T, int C, long n, int doRelu) {
    long idx = (long)blockIdx.x*blockDim.x + threadIdx.x;
    if (idx >= n) return;
    int bg = (int)(idx / groupSize);
    int c  = (int)((idx / T) % C);
    float v = x[idx];
    if (y) v += y[idx];
    v = (v - stats[bg*2])*stats[bg*2 + 1]*w[c] + bvec[c];
    if (doRelu) v = fmaxf(v, 0.f);
    out[idx] = v;
}

// ---------------- fused attention: S=Q^T K, mask, softmax, O = A V^T ----------------
// Grid: (Tq, NHEAD, B), 256 threads, dynamic smem. K buffer reused for V.
#define SM_Q   (32*68)
#define SM_K   (32*260)
#define SM_S   (68*260)
#define SMEM_FLOATS (SM_Q + SM_K + SM_S + 256)
#define SMEM_BYTES  (SMEM_FLOATS*4)

__global__ void attn_kernel(const float* __restrict__ gq, const float* __restrict__ gkv,
                            const float* __restrict__ gm, float* __restrict__ gout) {
    extern __shared__ float sm[];
    float* Qs  = sm;                 // [32][68]  (d padded 65->68, pad=0)
    float* KVs = Qs + SM_Q;          // [32][260] K, later reused for V
    float* S   = KVs + SM_K;         // [68][260]
    float* Ms  = S + SM_S;           // [256]

    int q = blockIdx.x, g = blockIdx.y, b = blockIdx.z;
    int tid = threadIdx.x;
    long qbase = ((long)(b*HID + g*EDIM)*TQ + q)*TD;
    long kbase = ((long)(b*2*HID + g*EDIM)*TQ + q)*TS;
    long vbase = kbase + (long)HID*TQ*TS;

    for (int i = tid; i < SM_Q; i += 256) {
        int e = i/68, d = i%68;
        Qs[i] = (d < TD) ? gq[qbase + (long)e*TQ*TD + d] : 0.f;
    }
    for (int i = tid; i < SM_K; i += 256) {
        int e = i/260, s = i%260;
        KVs[i] = (s < TS) ? gkv[kbase + (long)e*TQ*TS + s] : 0.f;
    }
    if (tid < 256) Ms[tid] = gm[b*256 + tid];
    __syncthreads();

    // S[d][s] = sum_e Q[e][d]*K[e][s], 4x4 register tiles over padded 68x260
    for (int t = tid; t < 17*65; t += 256) {
        int dt = t/65, st = t%65;
        float acc[4][4];
        #pragma unroll
        for (int i = 0; i < 4; i++)
            #pragma unroll
            for (int j = 0; j < 4; j++) acc[i][j] = 0.f;
        #pragma unroll
        for (int e = 0; e < 32; e++) {
            float4 a  = *(const float4*)&Qs[e*68 + dt*4];
            float4 k4 = *(const float4*)&KVs[e*260 + st*4];
            acc[0][0] += a.x*k4.x; acc[0][1] += a.x*k4.y; acc[0][2] += a.x*k4.z; acc[0][3] += a.x*k4.w;
            acc[1][0] += a.y*k4.x; acc[1][1] += a.y*k4.y; acc[1][2] += a.y*k4.z; acc[1][3] += a.y*k4.w;
            acc[2][0] += a.z*k4.x; acc[2][1] += a.z*k4.y; acc[2][2] += a.z*k4.z; acc[2][3] += a.z*k4.w;
            acc[3][0] += a.w*k4.x; acc[3][1] += a.w*k4.y; acc[3][2] += a.w*k4.z; acc[3][3] += a.w*k4.w;
        }
        #pragma unroll
        for (int i = 0; i < 4; i++)
            #pragma unroll
            for (int j = 0; j < 4; j++) {
                int s = st*4 + j;
                float v = acc[i][j];
                if (s >= 1 && s < TS && Ms[s-1] == 0.f) v = -1e9f;
                S[(dt*4 + i)*260 + s] = v;
            }
    }
    __syncthreads();

    // Load V into the K buffer (all threads), then softmax over the S rows.
    for (int i = tid; i < SM_K; i += 256) {
        int e = i/260, s = i%260;
        KVs[i] = (s < TS) ? gkv[vbase + (long)e*TQ*TS + s] : 0.f;
    }

    int wid = tid >> 5, lane = tid & 31;
    for (int d = wid; d < TD; d += 8) {
        float mx = -1e30f;
        for (int s = lane; s < TS; s += 32) mx = fmaxf(mx, S[d*260 + s]);
        #pragma unroll
        for (int o = 16; o > 0; o >>= 1) mx = fmaxf(mx, __shfl_xor_sync(0xffffffffu, mx, o));
        float sum = 0.f;
        for (int s = lane; s < TS; s += 32) {
            float e = expf(S[d*260 + s] - mx);
            S[d*260 + s] = e;
            sum += e;
        }
        #pragma unroll
        for (int o = 16; o > 0; o >>= 1) sum += __shfl_xor_sync(0xffffffffu, sum, o);
        float inv = 1.0f/sum;
        for (int s = lane; s < TS; s += 32) S[d*260 + s] *= inv;
        if (lane < 3) S[d*260 + TS + lane] = 0.f;
    }
    __syncthreads();

    // O[e][d] = sum_s A[d][s]*V[e][s]; 4e x 4d tiles, float4 over s
    long obase = qbase;
    for (int t = tid; t < 8*17; t += 256) {
        int et = t/17, dt = t%17;
        float acc[4][4];    // [e][d]
        #pragma unroll
        for (int j = 0; j < 4; j++)
            #pragma unroll
            for (int i = 0; i < 4; i++) acc[j][i] = 0.f;
        for (int s4 = 0; s4 < 65; s4++) {
            float4 a0 = *(const float4*)&S[(dt*4 + 0)*260 + s4*4];
            float4 a1 = *(const float4*)&S[(dt*4 + 1)*260 + s4*4];
            float4 a2 = *(const float4*)&S[(dt*4 + 2)*260 + s4*4];
            float4 a3 = *(const float4*)&S[(dt*4 + 3)*260 + s4*4];
            float4 v0 = *(const float4*)&KVs[(et*4 + 0)*260 + s4*4];
            float4 v1 = *(const float4*)&KVs[(et*4 + 1)*260 + s4*4];
            float4 v2 = *(const float4*)&KVs[(et*4 + 2)*260 + s4*4];
            float4 v3 = *(const float4*)&KVs[(et*4 + 3)*260 + s4*4];
            acc[0][0] += a0.x*v0.x + a0.y*v0.y + a0.z*v0.z + a0.w*v0.w;
            acc[0][1] += a1.x*v0.x + a1.y*v0.y + a1.z*v0.z + a1.w*v0.w;
            acc[0][2] += a2.x*v0.x + a2.y*v0.y + a2.z*v0.z + a2.w*v0.w;
            acc[0][3] += a3.x*v0.x + a3.y*v0.y + a3.z*v0.z + a3.w*v0.w;
            acc[1][0] += a0.x*v1.x + a0.y*v1.y + a0.z*v1.z + a0.w*v1.w;
            acc[1][1] += a1.x*v1.x + a1.y*v1.y + a1.z*v1.z + a1.w*v1.w;
            acc[1][2] += a2.x*v1.x + a2.y*v1.y + a2.z*v1.z + a2.w*v1.w;
            acc[1][3] += a3.x*v1.x + a3.y*v1.y + a3.z*v1.z + a3.w*v1.w;
            acc[2][0] += a0.x*v2.x + a0.y*v2.y + a0.z*v2.z + a0.w*v2.w;
            acc[2][1] += a1.x*v2.x + a1.y*v2.y + a1.z*v2.z + a1.w*v2.w;
            acc[2][2] += a2.x*v2.x + a2.y*v2.y + a2.z*v2.z + a2.w*v2.w;
            acc[2][3] += a3.x*v2.x + a3.y*v2.y + a3.z*v2.z + a3.w*v2.w;
            acc[3][0] += a0.x*v3.x + a0.y*v3.y + a0.z*v3.z + a0.w*v3.w;
            acc[3][1] += a1.x*v3.x + a1.y*v3.y + a1.z*v3.z + a1.w*v3.w;
            acc[3][2] += a2.x*v3.x + a2.y*v3.y + a2.z*v3.z + a2.w*v3.w;
            acc[3][3] += a3.x*v3.x + a3.y*v3.y + a3.z*v3.z + a3.w*v3.w;
        }
        #pragma unroll
        for (int j = 0; j < 4; j++)
            #pragma unroll
            for (int i = 0; i < 4; i++) {
                int d = dt*4 + i;
                if (d < TD)
                    gout[obase + (long)(et*4 + j)*TQ*TD + d] = acc[j][i];
            }
    }
}

// ---------------- host orchestration ----------------
static void run_gn(const float* x, const float* y, float* out,
                   const float* w, const float* bvec,
                   float* partial, float* stats,
                   int C, int T, int doRelu) {
    long groupSize = (long)(C/4)*T;
    long n = (long)BB*C*T;
    float invN = 1.0f/(float)groupSize;
    gn_reduce<<<dim3(128, 16), 256>>>(x, y, partial, groupSize);
    gn_finalize<<<1, 16>>>(partial, stats, 128, invN);
    gn_apply<<<(unsigned)((n + 255)/256), 256>>>(x, y, out, w, bvec, stats, groupSize, T, C, n, doRelu);
}

extern "C" void kernel_launch(void* const* d_in, const int* in_sizes, int n_in,
                              void* d_out, int out_size) {
    const float* corr   = (const float*)d_in[0];
    const int*   smask  = (const int*)  d_in[1];
    const float* W_sc   = (const float*)d_in[2];
    const float* gnscw  = (const float*)d_in[3];
    const float* gnscb  = (const float*)d_in[4];
    const float* W_qkv  = (const float*)d_in[5];
    const float* b_qkv  = (const float*)d_in[6];
    const float* gn1w   = (const float*)d_in[7];
    const float* gn1b   = (const float*)d_in[8];
    const float* W_agg  = (const float*)d_in[9];
    const float* gn2w   = (const float*)d_in[10];
    const float* gn2b   = (const float*)d_in[11];
    const float* gnow   = (const float*)d_in[12];
    const float* gnob   = (const float*)d_in[13];
    float* out = (float*)d_out;

    float *pooled, *kv, *q, *res, *att, *agg, *mask, *partial, *stats;
    cudaGetSymbolAddress((void**)&pooled, g_pooled);
    cudaGetSymbolAddress((void**)&kv,     g_kv);
    cudaGetSymbolAddress((void**)&q,      g_q);
    cudaGetSymbolAddress((void**)&res,    g_res);
    cudaGetSymbolAddress((void**)&att,    g_att);
    cudaGetSymbolAddress((void**)&agg,    g_agg);
    cudaGetSymbolAddress((void**)&mask,   g_mask);
    cudaGetSymbolAddress((void**)&partial,g_partial);
    cudaGetSymbolAddress((void**)&stats,  g_stats);

    const int NPOOL = TQ*TD;     // 16640 = 130*128
    const int NFULL = TQ*TS;     // 65792 = 514*128

    // 1. pooled corr + mask
    pool_kernel<<<(BB*CIN*TQ*TD + 255)/256, 256>>>(corr, pooled);
    mask_kernel<<<4, 256>>>(smask, mask);

    // 2. GEMMs: Q (pooled, +bias), residual-pre (pooled), fused K+V (full corr, +bias)
    gemm128<<<dim3(NPOOL/128, HID/128,   BB), 256>>>(W_qkv,           b_qkv,       pooled, q,   HID,   NPOOL, CIN);
    gemm128<<<dim3(NPOOL/128, COUT/128,  BB), 256>>>(W_sc,            nullptr,     pooled, res, COUT,  NPOOL, CIN);
    gemm128<<<dim3(NFULL/128, 2*HID/128, BB), 256>>>(W_qkv + HID*CIN, b_qkv + HID, corr,   kv,  2*HID, NFULL, CIN);

    // 3. residual = relu(gn_sc(res))
    run_gn(res, nullptr, res, gnscw, gnscb, partial, stats, COUT, NPOOL, 1);

    // 4. attention
    cudaFuncSetAttribute(attn_kernel, cudaFuncAttributeMaxDynamicSharedMemorySize, SMEM_BYTES);
    attn_kernel<<<dim3(TQ, NHEAD, BB), 256, SMEM_BYTES>>>(q, kv, mask, att);

    // 5. out = relu(gn1(att))
    run_gn(att, nullptr, att, gn1w, gn1b, partial, stats, HID, NPOOL, 1);

    // 6. agg = W_agg @ att
    gemm128<<<dim3(NPOOL/128, COUT/128, BB), 256>>>(W_agg, nullptr, att, agg, COUT, NPOOL, HID);

    // 7. agg = relu(gn2(agg))
    run_gn(agg, nullptr, agg, gn2w, gn2b, partial, stats, COUT, NPOOL, 1);

    // 8. out = gn_out(agg + res)
    run_gn(agg, res, out, gnow, gnob, partial, stats, COUT, NPOOL, 0);
}

// round 3
// speedup vs baseline: 1.7960x; 1.2527x over previous
#include <cuda_runtime.h>
#include <cuda_bf16.h>
#include <math.h>

#define BB 4
#define CIN 128
#define TQ 256
#define TS 257
#define TD 65
#define HID 256
#define COUT 512
#define NHEAD 8
#define EDIM 32

// ---------------- scratch (static device globals; no allocation) ----------------
__device__ float g_pooled[BB*CIN*TQ*TD];
__device__ float g_kv[BB*2*HID*TQ*TS];
__device__ float g_q[BB*HID*TQ*TD];
__device__ float g_res[BB*COUT*TQ*TD];
__device__ float g_att[BB*HID*TQ*TD];
__device__ float g_agg[BB*COUT*TQ*TD];
__device__ float g_mask[BB*256];
__device__ float g_partial[16*128*2];
__device__ float g_stats[16*2];

// ---------------- cst_pool on corr tokens ----------------
__global__ void pool_kernel(const float* __restrict__ in, float* __restrict__ out) {
    int idx = blockIdx.x*blockDim.x + threadIdx.x;
    const int n = BB*CIN*TQ*TD;
    if (idx >= n) return;
    int sp = idx % TD;
    int q  = (idx/TD) % TQ;
    int c  = (idx/(TD*TQ)) % CIN;
    int b  = idx/(TD*TQ*CIN);
    const float* src = in + ((long)(b*CIN + c)*TQ + q)*TS;
    float v;
    if (sp == 0) {
        v = src[0];
    } else {
        int t = sp - 1;
        int i = t >> 3, j = t & 7;
        const float* p = src + 1 + (i*2)*16 + j*2;
        v = 0.25f*(p[0] + p[1] + p[16] + p[17]);
    }
    out[idx] = v;
}

// ---------------- mask: exact bilinear subsample ----------------
__global__ void mask_kernel(const int* __restrict__ s, float* __restrict__ m) {
    int idx = blockIdx.x*blockDim.x + threadIdx.x;
    if (idx >= BB*256) return;
    int b = idx >> 8;
    int r = idx & 255;
    int i = r >> 4, j = r & 15;
    int v = s[b*65536 + (i*17)*256 + j*17];
    m[idx] = (v > 0) ? 1.0f : 0.0f;
}

// ---------------- bf16 split helpers ----------------
__device__ __forceinline__ unsigned pk2(float x, float y) {
    __nv_bfloat162 t = __floats2bfloat162_rn(x, y);
    return *(unsigned*)&t;
}
__device__ __forceinline__ float bflo(float x) {
    __nv_bfloat16 h = __float2bfloat16(x);
    return x - __bfloat162float(h);
}

#define LDMX4(r0,r1,r2,r3,addr) \
    asm volatile("ldmatrix.sync.aligned.m8n8.x4.shared.b16 {%0,%1,%2,%3}, [%4];" \
        : "=r"(r0),"=r"(r1),"=r"(r2),"=r"(r3) : "r"(addr))
#define LDMX2T(r0,r1,addr) \
    asm volatile("ldmatrix.sync.aligned.m8n8.x2.trans.shared.b16 {%0,%1}, [%2];" \
        : "=r"(r0),"=r"(r1) : "r"(addr))
#define MMA16816(c0,c1,c2,c3,a0,a1,a2,a3,b0,b1) \
    asm volatile("mma.sync.aligned.m16n8k16.row.col.f32.bf16.bf16.f32 " \
        "{%0,%1,%2,%3}, {%4,%5,%6,%7}, {%8,%9}, {%0,%1,%2,%3};" \
        : "+f"(c0),"+f"(c1),"+f"(c2),"+f"(c3) \
        : "r"(a0),"r"(a1),"r"(a2),"r"(a3),"r"(b0),"r"(b1))

// ---------------- tensor-core GEMM with 3-term bf16 split ----------------
// Y[b] = W @ X[b] (+bias). W: [M,K] rm, X: [B,K,N], Y: [B,M,N].
// Grid: (N/128, M/128, B), 256 threads. M%128==0, N%128==0, K%16==0.
#define STRA 24     // A smem row stride (bf16 units)
#define STRX 136    // X smem row stride (bf16 units)
#define ABUF (128*STRA)   // 3072
#define XBUF (16*STRX)    // 2176
#define BUFSZ (2*ABUF + 2*XBUF)

__global__ void __launch_bounds__(256, 2)
gemm_mma(const float* __restrict__ W, const float* __restrict__ bias,
         const float* __restrict__ X, float* __restrict__ Y,
         int M, int N, int K) {
    __shared__ __align__(16) unsigned short sm_[2*BUFSZ];

    int b  = blockIdx.z;
    const float* Xb = X + (long)b*K*N;
    float* Yb = Y + (long)b*M*N;
    int n0 = blockIdx.x*128, m0 = blockIdx.y*128;
    int tid = threadIdx.x;
    int wid = tid >> 5, lane = tid & 31;
    int warp_m = wid & 1, warp_n = wid >> 1;     // 2 x 4 warp grid, warp tile 64x32

    // global load maps
    int arow = tid >> 1, aq = tid & 1;                    // A: 128 rows x 16k
    const float* Ap = W + (long)(m0 + arow)*K + aq*8;
    int xk = tid >> 4, xn = (tid & 15)*4;                 // X: 16k x 128n
    const float* Xp = Xb + (long)xk*N + n0 + xn;

    // ldmatrix lane offsets
    int a_mrow = (lane & 7) + ((lane >> 3) & 1)*8;        // row within m16 tile
    int a_koff = ((lane >> 4) & 1)*8;                     // k half
    int b_krow = lane & 15;                               // row within k16 tile (x2)

    float acc[4][4][4];
    #pragma unroll
    for (int i = 0; i < 4; i++)
        #pragma unroll
        for (int j = 0; j < 4; j++)
            #pragma unroll
            for (int r = 0; r < 4; r++) acc[i][j][r] = 0.f;

    int nt_chunks = K >> 4;

    // prologue: load chunk 0
    {
        float4 a0 = *(const float4*)Ap;
        float4 a1 = *(const float4*)(Ap + 4);
        float4 x0 = *(const float4*)Xp;
        float4 x1 = *(const float4*)(Xp + 64);
        unsigned short* Ah = sm_;
        unsigned short* Al = Ah + ABUF;
        unsigned short* Xh = Ah + 2*ABUF;
        unsigned short* Xl = Xh + XBUF;
        *(uint2*)&Ah[arow*STRA + aq*8]     = make_uint2(pk2(a0.x,a0.y), pk2(a0.z,a0.w));
        *(uint2*)&Ah[arow*STRA + aq*8 + 4] = make_uint2(pk2(a1.x,a1.y), pk2(a1.z,a1.w));
        *(uint2*)&Al[arow*STRA + aq*8]     = make_uint2(pk2(bflo(a0.x),bflo(a0.y)), pk2(bflo(a0.z),bflo(a0.w)));
        *(uint2*)&Al[arow*STRA + aq*8 + 4] = make_uint2(pk2(bflo(a1.x),bflo(a1.y)), pk2(bflo(a1.z),bflo(a1.w)));
        *(uint2*)&Xh[xk*STRX + xn]      = make_uint2(pk2(x0.x,x0.y), pk2(x0.z,x0.w));
        *(uint2*)&Xh[xk*STRX + xn + 64] = make_uint2(pk2(x1.x,x1.y), pk2(x1.z,x1.w));
        *(uint2*)&Xl[xk*STRX + xn]      = make_uint2(pk2(bflo(x0.x),bflo(x0.y)), pk2(bflo(x0.z),bflo(x0.w)));
        *(uint2*)&Xl[xk*STRX + xn + 64] = make_uint2(pk2(bflo(x1.x),bflo(x1.y)), pk2(bflo(x1.z),bflo(x1.w)));
    }
    __syncthreads();

    for (int t = 0; t < nt_chunks; t++) {
        int cur = t & 1;
        float4 a0, a1, x0, x1;
        if (t + 1 < nt_chunks) {
            a0 = *(const float4*)(Ap + (t+1)*16);
            a1 = *(const float4*)(Ap + (t+1)*16 + 4);
            x0 = *(const float4*)(Xp + (long)(t+1)*16*N);
            x1 = *(const float4*)(Xp + (long)(t+1)*16*N + 64);
        }

        const unsigned short* Ah = sm_ + cur*BUFSZ;
        const unsigned short* Al = Ah + ABUF;
        const unsigned short* Xh = Ah + 2*ABUF;
        const unsigned short* Xl = Xh + XBUF;

        // B fragments for this warp's 4 n-tiles (hi and lo)
        unsigned bh[4][2], bl[4][2];
        #pragma unroll
        for (int nt = 0; nt < 4; nt++) {
            int col = warp_n*32 + nt*8;
            unsigned ad = (unsigned)__cvta_generic_to_shared(&Xh[b_krow*STRX + col]);
            LDMX2T(bh[nt][0], bh[nt][1], ad);
            ad = (unsigned)__cvta_generic_to_shared(&Xl[b_krow*STRX + col]);
            LDMX2T(bl[nt][0], bl[nt][1], ad);
        }

        #pragma unroll
        for (int mt = 0; mt < 4; mt++) {
            int row = warp_m*64 + mt*16 + a_mrow;
            unsigned ah0,ah1,ah2,ah3, al0,al1,al2,al3;
            unsigned ad = (unsigned)__cvta_generic_to_shared(&Ah[row*STRA + a_koff]);
            LDMX4(ah0,ah1,ah2,ah3, ad);
            ad = (unsigned)__cvta_generic_to_shared(&Al[row*STRA + a_koff]);
            LDMX4(al0,al1,al2,al3, ad);
            #pragma unroll
            for (int nt = 0; nt < 4; nt++) {
                float* c = acc[mt][nt];
                MMA16816(c[0],c[1],c[2],c[3], ah0,ah1,ah2,ah3, bh[nt][0],bh[nt][1]);
                MMA16816(c[0],c[1],c[2],c[3], ah0,ah1,ah2,ah3, bl[nt][0],bl[nt][1]);
                MMA16816(c[0],c[1],c[2],c[3], al0,al1,al2,al3, bh[nt][0],bh[nt][1]);
            }
        }

        if (t + 1 < nt_chunks) {
            int nxt = cur ^ 1;
            unsigned short* Ah2 = sm_ + nxt*BUFSZ;
            unsigned short* Al2 = Ah2 + ABUF;
            unsigned short* Xh2 = Ah2 + 2*ABUF;
            unsigned short* Xl2 = Xh2 + XBUF;
            *(uint2*)&Ah2[arow*STRA + aq*8]     = make_uint2(pk2(a0.x,a0.y), pk2(a0.z,a0.w));
            *(uint2*)&Ah2[arow*STRA + aq*8 + 4] = make_uint2(pk2(a1.x,a1.y), pk2(a1.z,a1.w));
            *(uint2*)&Al2[arow*STRA + aq*8]     = make_uint2(pk2(bflo(a0.x),bflo(a0.y)), pk2(bflo(a0.z),bflo(a0.w)));
            *(uint2*)&Al2[arow*STRA + aq*8 + 4] = make_uint2(pk2(bflo(a1.x),bflo(a1.y)), pk2(bflo(a1.z),bflo(a1.w)));
            *(uint2*)&Xh2[xk*STRX + xn]      = make_uint2(pk2(x0.x,x0.y), pk2(x0.z,x0.w));
            *(uint2*)&Xh2[xk*STRX + xn + 64] = make_uint2(pk2(x1.x,x1.y), pk2(x1.z,x1.w));
            *(uint2*)&Xl2[xk*STRX + xn]      = make_uint2(pk2(bflo(x0.x),bflo(x0.y)), pk2(bflo(x0.z),bflo(x0.w)));
            *(uint2*)&Xl2[xk*STRX + xn + 64] = make_uint2(pk2(bflo(x1.x),bflo(x1.y)), pk2(bflo(x1.z),bflo(x1.w)));
            __syncthreads();
        }
    }

    // epilogue
    int g = lane >> 2, tq = lane & 3;
    #pragma unroll
    for (int mt = 0; mt < 4; mt++) {
        int r0 = m0 + warp_m*64 + mt*16 + g;
        float b0v = bias ? bias[r0]   : 0.f;
        float b1v = bias ? bias[r0+8] : 0.f;
        #pragma unroll
        for (int nt = 0; nt < 4; nt++) {
            int c = n0 + warp_n*32 + nt*8 + tq*2;
            float* a = acc[mt][nt];
            *(float2*)&Yb[(long)r0*N + c]     = make_float2(a[0]+b0v, a[1]+b0v);
            *(float2*)&Yb[(long)(r0+8)*N + c] = make_float2(a[2]+b1v, a[3]+b1v);
        }
    }
}

// ---------------- GroupNorm: 2-stage deterministic reduce + apply ----------------
__global__ void gn_reduce(const float* __restrict__ x, const float* __restrict__ y,
                          float* __restrict__ partial, long groupSize) {
    long bg = blockIdx.y;
    long base = bg*groupSize;
    int tid = threadIdx.x;
    float s1 = 0.f, s2 = 0.f;
    for (long i = (long)blockIdx.x*blockDim.x + tid; i < groupSize; i += (long)gridDim.x*blockDim.x) {
        float v = x[base + i];
        if (y) v += y[base + i];
        s1 += v; s2 += v*v;
    }
    __shared__ float sh1[256], sh2[256];
    sh1[tid] = s1; sh2[tid] = s2;
    __syncthreads();
    for (int o = 128; o > 0; o >>= 1) {
        if (tid < o) { sh1[tid] += sh1[tid+o]; sh2[tid] += sh2[tid+o]; }
        __syncthreads();
    }
    if (tid == 0) {
        partial[(bg*gridDim.x + blockIdx.x)*2 + 0] = sh1[0];
        partial[(bg*gridDim.x + blockIdx.x)*2 + 1] = sh2[0];
    }
}

__global__ void gn_finalize(const float* __restrict__ partial, float* __restrict__ stats,
                            int nb, float invN) {
    int bg = threadIdx.x;
    if (bg >= 16) return;
    float s1 = 0.f, s2 = 0.f;
    for (int i = 0; i < nb; i++) {
        s1 += partial[(bg*nb + i)*2 + 0];
        s2 += partial[(bg*nb + i)*2 + 1];
    }
    float mean = s1*invN;
    float var  = fmaxf(s2*invN - mean*mean, 0.f);
    stats[bg*2 + 0] = mean;
    stats[bg*2 + 1] = 1.0f/sqrtf(var + 1e-5f);
}

__global__ void gn_apply(const float* __restrict__ x, const float* __restrict__ y,
                         float* __restrict__ out,
                         const float* __restrict__ w, const float* __restrict__ bvec,
                         const float* __restrict__ stats,
                         long groupSize, int T, int C, long n, int doRelu) {
    long idx = (long)blockIdx.x*blockDim.x + threadIdx.x;
    if (idx >= n) return;
    int bg = (int)(idx / groupSize);
    int c  = (int)((idx / T) % C);
    float v = x[idx];
    if (y) v += y[idx];
    v = (v - stats[bg*2])*stats[bg*2 + 1]*w[c] + bvec[c];
    if (doRelu) v = fmaxf(v, 0.f);
    out[idx] = v;
}

// ---------------- fused attention ----------------
#define SM_Q   (32*68)
#define SM_K   (32*260)
#define SM_S   (68*260)
#define SMEM_FLOATS (SM_Q + SM_K + SM_S + 256)
#define SMEM_BYTES  (SMEM_FLOATS*4)

__global__ void attn_kernel(const float* __restrict__ gq, const float* __restrict__ gkv,
                            const float* __restrict__ gm, float* __restrict__ gout) {
    extern __shared__ float sm[];
    float* Qs  = sm;
    float* KVs = Qs + SM_Q;
    float* S   = KVs + SM_K;
    float* Ms  = S + SM_S;

    int q = blockIdx.x, g = blockIdx.y, b = blockIdx.z;
    int tid = threadIdx.x;
    long qbase = ((long)(b*HID + g*EDIM)*TQ + q)*TD;
    long kbase = ((long)(b*2*HID + g*EDIM)*TQ + q)*TS;
    long vbase = kbase + (long)HID*TQ*TS;

    for (int i = tid; i < SM_Q; i += 256) {
        int e = i/68, d = i%68;
        Qs[i] = (d < TD) ? gq[qbase + (long)e*TQ*TD + d] : 0.f;
    }
    for (int i = tid; i < SM_K; i += 256) {
        int e = i/260, s = i%260;
        KVs[i] = (s < TS) ? gkv[kbase + (long)e*TQ*TS + s] : 0.f;
    }
    if (tid < 256) Ms[tid] = gm[b*256 + tid];
    __syncthreads();

    for (int t = tid; t < 17*65; t += 256) {
        int dt = t/65, st = t%65;
        float acc[4][4];
        #pragma unroll
        for (int i = 0; i < 4; i++)
            #pragma unroll
            for (int j = 0; j < 4; j++) acc[i][j] = 0.f;
        #pragma unroll
        for (int e = 0; e < 32; e++) {
            float4 a  = *(const float4*)&Qs[e*68 + dt*4];
            float4 k4 = *(const float4*)&KVs[e*260 + st*4];
            acc[0][0] += a.x*k4.x; acc[0][1] += a.x*k4.y; acc[0][2] += a.x*k4.z; acc[0][3] += a.x*k4.w;
            acc[1][0] += a.y*k4.x; acc[1][1] += a.y*k4.y; acc[1][2] += a.y*k4.z; acc[1][3] += a.y*k4.w;
            acc[2][0] += a.z*k4.x; acc[2][1] += a.z*k4.y; acc[2][2] += a.z*k4.z; acc[2][3] += a.z*k4.w;
            acc[3][0] += a.w*k4.x; acc[3][1] += a.w*k4.y; acc[3][2] += a.w*k4.z; acc[3][3] += a.w*k4.w;
        }
        #pragma unroll
        for (int i = 0; i < 4; i++)
            #pragma unroll
            for (int j = 0; j < 4; j++) {
                int s = st*4 + j;
                float v = acc[i][j];
                if (s >= 1 && s < TS && Ms[s-1] == 0.f) v = -1e9f;
                S[(dt*4 + i)*260 + s] = v;
            }
    }
    __syncthreads();

    for (int i = tid; i < SM_K; i += 256) {
        int e = i/260, s = i%260;
        KVs[i] = (s < TS) ? gkv[vbase + (long)e*TQ*TS + s] : 0.f;
    }

    int wid = tid >> 5, lane = tid & 31;
    for (int d = wid; d < TD; d += 8) {
        float mx = -1e30f;
        for (int s = lane; s < TS; s += 32) mx = fmaxf(mx, S[d*260 + s]);
        #pragma unroll
        for (int o = 16; o > 0; o >>= 1) mx = fmaxf(mx, __shfl_xor_sync(0xffffffffu, mx, o));
        float sum = 0.f;
        for (int s = lane; s < TS; s += 32) {
            float e = expf(S[d*260 + s] - mx);
            S[d*260 + s] = e;
            sum += e;
        }
        #pragma unroll
        for (int o = 16; o > 0; o >>= 1) sum += __shfl_xor_sync(0xffffffffu, sum, o);
        float inv = 1.0f/sum;
        for (int s = lane; s < TS; s += 32) S[d*260 + s] *= inv;
        if (lane < 3) S[d*260 + TS + lane] = 0.f;
    }
    __syncthreads();

    long obase = qbase;
    for (int t = tid; t < 8*17; t += 256) {
        int et = t/17, dt = t%17;
        float acc[4][4];
        #pragma unroll
        for (int j = 0; j < 4; j++)
            #pragma unroll
            for (int i = 0; i < 4; i++) acc[j][i] = 0.f;
        for (int s4 = 0; s4 < 65; s4++) {
            float4 a0 = *(const float4*)&S[(dt*4 + 0)*260 + s4*4];
            float4 a1 = *(const float4*)&S[(dt*4 + 1)*260 + s4*4];
            float4 a2 = *(const float4*)&S[(dt*4 + 2)*260 + s4*4];
            float4 a3 = *(const float4*)&S[(dt*4 + 3)*260 + s4*4];
            float4 v0 = *(const float4*)&KVs[(et*4 + 0)*260 + s4*4];
            float4 v1 = *(const float4*)&KVs[(et*4 + 1)*260 + s4*4];
            float4 v2 = *(const float4*)&KVs[(et*4 + 2)*260 + s4*4];
            float4 v3 = *(const float4*)&KVs[(et*4 + 3)*260 + s4*4];
            acc[0][0] += a0.x*v0.x + a0.y*v0.y + a0.z*v0.z + a0.w*v0.w;
            acc[0][1] += a1.x*v0.x + a1.y*v0.y + a1.z*v0.z + a1.w*v0.w;
            acc[0][2] += a2.x*v0.x + a2.y*v0.y + a2.z*v0.z + a2.w*v0.w;
            acc[0][3] += a3.x*v0.x + a3.y*v0.y + a3.z*v0.z + a3.w*v0.w;
            acc[1][0] += a0.x*v1.x + a0.y*v1.y + a0.z*v1.z + a0.w*v1.w;
            acc[1][1] += a1.x*v1.x + a1.y*v1.y + a1.z*v1.z + a1.w*v1.w;
            acc[1][2] += a2.x*v1.x + a2.y*v1.y + a2.z*v1.z + a2.w*v1.w;
            acc[1][3] += a3.x*v1.x + a3.y*v1.y + a3.z*v1.z + a3.w*v1.w;
            acc[2][0] += a0.x*v2.x + a0.y*v2.y + a0.z*v2.z + a0.w*v2.w;
            acc[2][1] += a1.x*v2.x + a1.y*v2.y + a1.z*v2.z + a1.w*v2.w;
            acc[2][2] += a2.x*v2.x + a2.y*v2.y + a2.z*v2.z + a2.w*v2.w;
            acc[2][3] += a3.x*v2.x + a3.y*v2.y + a3.z*v2.z + a3.w*v2.w;
            acc[3][0] += a0.x*v3.x + a0.y*v3.y + a0.z*v3.z + a0.w*v3.w;
            acc[3][1] += a1.x*v3.x + a1.y*v3.y + a1.z*v3.z + a1.w*v3.w;
            acc[3][2] += a2.x*v3.x + a2.y*v3.y + a2.z*v3.z + a2.w*v3.w;
            acc[3][3] += a3.x*v3.x + a3.y*v3.y + a3.z*v3.z + a3.w*v3.w;
        }
        #pragma unroll
        for (int j = 0; j < 4; j++)
            #pragma unroll
            for (int i = 0; i < 4; i++) {
                int d = dt*4 + i;
                if (d < TD)
                    gout[obase + (long)(et*4 + j)*TQ*TD + d] = acc[j][i];
            }
    }
}

// ---------------- host orchestration ----------------
static void run_gn(const float* x, const float* y, float* out,
                   const float* w, const float* bvec,
                   float* partial, float* stats,
                   int C, int T, int doRelu) {
    long groupSize = (long)(C/4)*T;
    long n = (long)BB*C*T;
    float invN = 1.0f/(float)groupSize;
    gn_reduce<<<dim3(128, 16), 256>>>(x, y, partial, groupSize);
    gn_finalize<<<1, 16>>>(partial, stats, 128, invN);
    gn_apply<<<(unsigned)((n + 255)/256), 256>>>(x, y, out, w, bvec, stats, groupSize, T, C, n, doRelu);
}

extern "C" void kernel_launch(void* const* d_in, const int* in_sizes, int n_in,
                              void* d_out, int out_size) {
    const float* corr   = (const float*)d_in[0];
    const int*   smask  = (const int*)  d_in[1];
    const float* W_sc   = (const float*)d_in[2];
    const float* gnscw  = (const float*)d_in[3];
    const float* gnscb  = (const float*)d_in[4];
    const float* W_qkv  = (const float*)d_in[5];
    const float* b_qkv  = (const float*)d_in[6];
    const float* gn1w   = (const float*)d_in[7];
    const float* gn1b   = (const float*)d_in[8];
    const float* W_agg  = (const float*)d_in[9];
    const float* gn2w   = (const float*)d_in[10];
    const float* gn2b   = (const float*)d_in[11];
    const float* gnow   = (const float*)d_in[12];
    const float* gnob   = (const float*)d_in[13];
    float* out = (float*)d_out;

    float *pooled, *kv, *q, *res, *att, *agg, *mask, *partial, *stats;
    cudaGetSymbolAddress((void**)&pooled, g_pooled);
    cudaGetSymbolAddress((void**)&kv,     g_kv);
    cudaGetSymbolAddress((void**)&q,      g_q);
    cudaGetSymbolAddress((void**)&res,    g_res);
    cudaGetSymbolAddress((void**)&att,    g_att);
    cudaGetSymbolAddress((void**)&agg,    g_agg);
    cudaGetSymbolAddress((void**)&mask,   g_mask);
    cudaGetSymbolAddress((void**)&partial,g_partial);
    cudaGetSymbolAddress((void**)&stats,  g_stats);

    const int NPOOL = TQ*TD;     // 16640 = 130*128
    const int NFULL = TQ*TS;     // 65792 = 514*128

    // 1. pooled corr + mask
    pool_kernel<<<(BB*CIN*TQ*TD + 255)/256, 256>>>(corr, pooled);
    mask_kernel<<<4, 256>>>(smask, mask);

    // 2. GEMMs (tensor cores): Q (pooled, +bias), res (pooled), fused K+V (full corr, +bias)
    gemm_mma<<<dim3(NPOOL/128, HID/128,   BB), 256>>>(W_qkv,           b_qkv,       pooled, q,   HID,   NPOOL, CIN);
    gemm_mma<<<dim3(NPOOL/128, COUT/128,  BB), 256>>>(W_sc,            nullptr,     pooled, res, COUT,  NPOOL, CIN);
    gemm_mma<<<dim3(NFULL/128, 2*HID/128, BB), 256>>>(W_qkv + HID*CIN, b_qkv + HID, corr,   kv,  2*HID, NFULL, CIN);

    // 3. residual = relu(gn_sc(res))
    run_gn(res, nullptr, res, gnscw, gnscb, partial, stats, COUT, NPOOL, 1);

    // 4. attention
    cudaFuncSetAttribute(attn_kernel, cudaFuncAttributeMaxDynamicSharedMemorySize, SMEM_BYTES);
    attn_kernel<<<dim3(TQ, NHEAD, BB), 256, SMEM_BYTES>>>(q, kv, mask, att);

    // 5. out = relu(gn1(att))
    run_gn(att, nullptr, att, gn1w, gn1b, partial, stats, HID, NPOOL, 1);

    // 6. agg = W_agg @ att
    gemm_mma<<<dim3(NPOOL/128, COUT/128, BB), 256>>>(W_agg, nullptr, att, agg, COUT, NPOOL, HID);

    // 7. agg = relu(gn2(agg))
    run_gn(agg, nullptr, agg, gn2w, gn2b, partial, stats, COUT, NPOOL, 1);

    // 8. out = gn_out(agg + res)
    run_gn(agg, res, out, gnow, gnob, partial, stats, COUT, NPOOL, 0);
}

// round 4
// speedup vs baseline: 2.1728x; 1.2098x over previous
#include <cuda_runtime.h>
#include <cuda_bf16.h>
#include <math.h>

#define BB 4
#define CIN 128
#define TQ 256
#define TS 257
#define TD 65
#define HID 256
#define COUT 512
#define NHEAD 8
#define EDIM 32

// ---------------- scratch (static device globals; no allocation) ----------------
__device__ float g_pooled[BB*CIN*TQ*TD];
__device__ float g_kv[BB*2*HID*TQ*TS];
__device__ float g_q[BB*HID*TQ*TD];
__device__ float g_res[BB*COUT*TQ*TD];
__device__ float g_att[BB*HID*TQ*TD];
__device__ float g_agg[BB*COUT*TQ*TD];
__device__ int   g_sidx[BB*260];
__device__ int   g_cnt[BB];
__device__ float g_partial[16*128*2];
__device__ float g_stats[16*2];

// ---------------- cst_pool: warp-per-row, smem staging ----------------
__global__ void pool_kernel2(const float* __restrict__ in, float* __restrict__ out) {
    __shared__ float row[8][260];
    int wid = threadIdx.x >> 5, lane = threadIdx.x & 31;
    long r = (long)blockIdx.x*8 + wid;      // row id in [0, BB*CIN*TQ)
    const float* src = in + r*TS;
    for (int i = lane; i < TS; i += 32) row[wid][i] = src[i];
    __syncwarp();
    float* dst = out + r*TD;
    if (lane == 0) dst[0] = row[wid][0];
    #pragma unroll
    for (int t = lane; t < 64; t += 32) {
        int i = t >> 3, j = t & 7;
        const float* p = &row[wid][1 + i*32 + j*2];
        dst[1 + t] = 0.25f*(p[0] + p[1] + p[16] + p[17]);
    }
}

// ---------------- mask: exact bilinear subsample + active-column compaction ----------------
__global__ void mask_compact(const int* __restrict__ s, int* __restrict__ sidx, int* __restrict__ cnt) {
    int b = blockIdx.x;
    int tid = threadIdx.x;
    int i = tid >> 4, j = tid & 15;
    int act = (s[b*65536 + (i*17)*256 + j*17] > 0) ? 1 : 0;
    __shared__ int sh[256];
    sh[tid] = act;
    __syncthreads();
    for (int off = 1; off < 256; off <<= 1) {
        int v = (tid >= off) ? sh[tid - off] : 0;
        __syncthreads();
        sh[tid] += v;
        __syncthreads();
    }
    if (act) sidx[b*260 + sh[tid]] = tid + 1;    // 1-based s position; slot 1+rank
    if (tid == 255) cnt[b] = sh[255] + 1;
    if (tid == 0) sidx[b*260] = 0;               // cls always active
}

// ---------------- bf16 split helpers ----------------
__device__ __forceinline__ unsigned pk2(float x, float y) {
    __nv_bfloat162 t = __floats2bfloat162_rn(x, y);
    return *(unsigned*)&t;
}
__device__ __forceinline__ float bflo(float x) {
    __nv_bfloat16 h = __float2bfloat16(x);
    return x - __bfloat162float(h);
}

#define LDMX4(r0,r1,r2,r3,addr) \
    asm volatile("ldmatrix.sync.aligned.m8n8.x4.shared.b16 {%0,%1,%2,%3}, [%4];" \
        : "=r"(r0),"=r"(r1),"=r"(r2),"=r"(r3) : "r"(addr))
#define LDMX2T(r0,r1,addr) \
    asm volatile("ldmatrix.sync.aligned.m8n8.x2.trans.shared.b16 {%0,%1}, [%2];" \
        : "=r"(r0),"=r"(r1) : "r"(addr))
#define MMA16816(c0,c1,c2,c3,a0,a1,a2,a3,b0,b1) \
    asm volatile("mma.sync.aligned.m16n8k16.row.col.f32.bf16.bf16.f32 " \
        "{%0,%1,%2,%3}, {%4,%5,%6,%7}, {%8,%9}, {%0,%1,%2,%3};" \
        : "+f"(c0),"+f"(c1),"+f"(c2),"+f"(c3) \
        : "r"(a0),"r"(a1),"r"(a2),"r"(a3),"r"(b0),"r"(b1))

// ---------------- tensor-core GEMM with 3-term bf16 split ----------------
#define STRA 24
#define STRX 136
#define ABUF (128*STRA)
#define XBUF (16*STRX)
#define BUFSZ (2*ABUF + 2*XBUF)

__global__ void __launch_bounds__(256, 2)
gemm_mma(const float* __restrict__ W, const float* __restrict__ bias,
         const float* __restrict__ X, float* __restrict__ Y,
         int M, int N, int K) {
    __shared__ __align__(16) unsigned short sm_[2*BUFSZ];

    int b  = blockIdx.z;
    const float* Xb = X + (long)b*K*N;
    float* Yb = Y + (long)b*M*N;
    int n0 = blockIdx.x*128, m0 = blockIdx.y*128;
    int tid = threadIdx.x;
    int wid = tid >> 5, lane = tid & 31;
    int warp_m = wid & 1, warp_n = wid >> 1;

    int arow = tid >> 1, aq = tid & 1;
    const float* Ap = W + (long)(m0 + arow)*K + aq*8;
    int xk = tid >> 4, xn = (tid & 15)*4;
    const float* Xp = Xb + (long)xk*N + n0 + xn;

    int a_mrow = (lane & 7) + ((lane >> 3) & 1)*8;
    int a_koff = ((lane >> 4) & 1)*8;
    int b_krow = lane & 15;

    float acc[4][4][4];
    #pragma unroll
    for (int i = 0; i < 4; i++)
        #pragma unroll
        for (int j = 0; j < 4; j++)
            #pragma unroll
            for (int r = 0; r < 4; r++) acc[i][j][r] = 0.f;

    int nt_chunks = K >> 4;
    {
        float4 a0 = *(const float4*)Ap;
        float4 a1 = *(const float4*)(Ap + 4);
        float4 x0 = *(const float4*)Xp;
        float4 x1 = *(const float4*)(Xp + 64);
        unsigned short* Ah = sm_;
        unsigned short* Al = Ah + ABUF;
        unsigned short* Xh = Ah + 2*ABUF;
        unsigned short* Xl = Xh + XBUF;
        *(uint2*)&Ah[arow*STRA + aq*8]     = make_uint2(pk2(a0.x,a0.y), pk2(a0.z,a0.w));
        *(uint2*)&Ah[arow*STRA + aq*8 + 4] = make_uint2(pk2(a1.x,a1.y), pk2(a1.z,a1.w));
        *(uint2*)&Al[arow*STRA + aq*8]     = make_uint2(pk2(bflo(a0.x),bflo(a0.y)), pk2(bflo(a0.z),bflo(a0.w)));
        *(uint2*)&Al[arow*STRA + aq*8 + 4] = make_uint2(pk2(bflo(a1.x),bflo(a1.y)), pk2(bflo(a1.z),bflo(a1.w)));
        *(uint2*)&Xh[xk*STRX + xn]      = make_uint2(pk2(x0.x,x0.y), pk2(x0.z,x0.w));
        *(uint2*)&Xh[xk*STRX + xn + 64] = make_uint2(pk2(x1.x,x1.y), pk2(x1.z,x1.w));
        *(uint2*)&Xl[xk*STRX + xn]      = make_uint2(pk2(bflo(x0.x),bflo(x0.y)), pk2(bflo(x0.z),bflo(x0.w)));
        *(uint2*)&Xl[xk*STRX + xn + 64] = make_uint2(pk2(bflo(x1.x),bflo(x1.y)), pk2(bflo(x1.z),bflo(x1.w)));
    }
    __syncthreads();

    for (int t = 0; t < nt_chunks; t++) {
        int cur = t & 1;
        float4 a0, a1, x0, x1;
        if (t + 1 < nt_chunks) {
            a0 = *(const float4*)(Ap + (t+1)*16);
            a1 = *(const float4*)(Ap + (t+1)*16 + 4);
            x0 = *(const float4*)(Xp + (long)(t+1)*16*N);
            x1 = *(const float4*)(Xp + (long)(t+1)*16*N + 64);
        }

        const unsigned short* Ah = sm_ + cur*BUFSZ;
        const unsigned short* Al = Ah + ABUF;
        const unsigned short* Xh = Ah + 2*ABUF;
        const unsigned short* Xl = Xh + XBUF;

        unsigned bh[4][2], bl[4][2];
        #pragma unroll
        for (int nt = 0; nt < 4; nt++) {
            int col = warp_n*32 + nt*8;
            unsigned ad = (unsigned)__cvta_generic_to_shared(&Xh[b_krow*STRX + col]);
            LDMX2T(bh[nt][0], bh[nt][1], ad);
            ad = (unsigned)__cvta_generic_to_shared(&Xl[b_krow*STRX + col]);
            LDMX2T(bl[nt][0], bl[nt][1], ad);
        }

        #pragma unroll
        for (int mt = 0; mt < 4; mt++) {
            int row = warp_m*64 + mt*16 + a_mrow;
            unsigned ah0,ah1,ah2,ah3, al0,al1,al2,al3;
            unsigned ad = (unsigned)__cvta_generic_to_shared(&Ah[row*STRA + a_koff]);
            LDMX4(ah0,ah1,ah2,ah3, ad);
            ad = (unsigned)__cvta_generic_to_shared(&Al[row*STRA + a_koff]);
            LDMX4(al0,al1,al2,al3, ad);
            #pragma unroll
            for (int nt = 0; nt < 4; nt++) {
                float* c = acc[mt][nt];
                MMA16816(c[0],c[1],c[2],c[3], ah0,ah1,ah2,ah3, bh[nt][0],bh[nt][1]);
                MMA16816(c[0],c[1],c[2],c[3], ah0,ah1,ah2,ah3, bl[nt][0],bl[nt][1]);
                MMA16816(c[0],c[1],c[2],c[3], al0,al1,al2,al3, bh[nt][0],bh[nt][1]);
            }
        }

        if (t + 1 < nt_chunks) {
            int nxt = cur ^ 1;
            unsigned short* Ah2 = sm_ + nxt*BUFSZ;
            unsigned short* Al2 = Ah2 + ABUF;
            unsigned short* Xh2 = Ah2 + 2*ABUF;
            unsigned short* Xl2 = Xh2 + XBUF;
            *(uint2*)&Ah2[arow*STRA + aq*8]     = make_uint2(pk2(a0.x,a0.y), pk2(a0.z,a0.w));
            *(uint2*)&Ah2[arow*STRA + aq*8 + 4] = make_uint2(pk2(a1.x,a1.y), pk2(a1.z,a1.w));
            *(uint2*)&Al2[arow*STRA + aq*8]     = make_uint2(pk2(bflo(a0.x),bflo(a0.y)), pk2(bflo(a0.z),bflo(a0.w)));
            *(uint2*)&Al2[arow*STRA + aq*8 + 4] = make_uint2(pk2(bflo(a1.x),bflo(a1.y)), pk2(bflo(a1.z),bflo(a1.w)));
            *(uint2*)&Xh2[xk*STRX + xn]      = make_uint2(pk2(x0.x,x0.y), pk2(x0.z,x0.w));
            *(uint2*)&Xh2[xk*STRX + xn + 64] = make_uint2(pk2(x1.x,x1.y), pk2(x1.z,x1.w));
            *(uint2*)&Xl2[xk*STRX + xn]      = make_uint2(pk2(bflo(x0.x),bflo(x0.y)), pk2(bflo(x0.z),bflo(x0.w)));
            *(uint2*)&Xl2[xk*STRX + xn + 64] = make_uint2(pk2(bflo(x1.x),bflo(x1.y)), pk2(bflo(x1.z),bflo(x1.w)));
            __syncthreads();
        }
    }

    int g = lane >> 2, tq = lane & 3;
    #pragma unroll
    for (int mt = 0; mt < 4; mt++) {
        int r0 = m0 + warp_m*64 + mt*16 + g;
        float b0v = bias ? bias[r0]   : 0.f;
        float b1v = bias ? bias[r0+8] : 0.f;
        #pragma unroll
        for (int nt = 0; nt < 4; nt++) {
            int c = n0 + warp_n*32 + nt*8 + tq*2;
            float* a = acc[mt][nt];
            *(float2*)&Yb[(long)r0*N + c]     = make_float2(a[0]+b0v, a[1]+b0v);
            *(float2*)&Yb[(long)(r0+8)*N + c] = make_float2(a[2]+b1v, a[3]+b1v);
        }
    }
}

// ---------------- GroupNorm kernels ----------------
__global__ void gn_reduce(const float* __restrict__ x, const float* __restrict__ y,
                          float* __restrict__ partial, long groupSize) {
    long bg = blockIdx.y;
    long base = bg*groupSize;
    int tid = threadIdx.x;
    float s1 = 0.f, s2 = 0.f;
    for (long i = (long)blockIdx.x*blockDim.x + tid; i < groupSize; i += (long)gridDim.x*blockDim.x) {
        float v = x[base + i];
        if (y) v += y[base + i];
        s1 += v; s2 += v*v;
    }
    __shared__ float sh1[256], sh2[256];
    sh1[tid] = s1; sh2[tid] = s2;
    __syncthreads();
    for (int o = 128; o > 0; o >>= 1) {
        if (tid < o) { sh1[tid] += sh1[tid+o]; sh2[tid] += sh2[tid+o]; }
        __syncthreads();
    }
    if (tid == 0) {
        partial[(bg*gridDim.x + blockIdx.x)*2 + 0] = sh1[0];
        partial[(bg*gridDim.x + blockIdx.x)*2 + 1] = sh2[0];
    }
}

__global__ void gn_finalize(const float* __restrict__ partial, float* __restrict__ stats,
                            int nb, float invN) {
    int bg = threadIdx.x;
    if (bg >= 16) return;
    float s1 = 0.f, s2 = 0.f;
    for (int i = 0; i < nb; i++) {
        s1 += partial[(bg*nb + i)*2 + 0];
        s2 += partial[(bg*nb + i)*2 + 1];
    }
    float mean = s1*invN;
    float var  = fmaxf(s2*invN - mean*mean, 0.f);
    stats[bg*2 + 0] = mean;
    stats[bg*2 + 1] = 1.0f/sqrtf(var + 1e-5f);
}

__global__ void gn_apply(const float* __restrict__ x, const float* __restrict__ y,
                         float* __restrict__ out,
                         const float* __restrict__ w, const float* __restrict__ bvec,
                         const float* __restrict__ stats,
                         long groupSize, int T, int C, long n, int doRelu) {
    long idx = (long)blockIdx.x*blockDim.x + threadIdx.x;
    if (idx >= n) return;
    int bg = (int)(idx / groupSize);
    int c  = (int)((idx / T) % C);
    float v = x[idx];
    if (y) v += y[idx];
    v = (v - stats[bg*2])*stats[bg*2 + 1]*w[c] + bvec[c];
    if (doRelu) v = fmaxf(v, 0.f);
    out[idx] = v;
}

// Fused: t = relu(gn2(agg)) + res (written over res), plus reduce sums of t for gn_out.
__global__ void gn_fuse(const float* __restrict__ agg, float* __restrict__ res_t,
                        const float* __restrict__ w, const float* __restrict__ bvec,
                        const float* __restrict__ stats, float* __restrict__ partial,
                        long groupSize, int T, int C) {
    long bg = blockIdx.y;
    long base = bg*groupSize;
    float mu = stats[bg*2], inv = stats[bg*2 + 1];
    int tid = threadIdx.x;
    float s1 = 0.f, s2 = 0.f;
    for (long i = (long)blockIdx.x*blockDim.x + tid; i < groupSize; i += (long)gridDim.x*blockDim.x) {
        long idx = base + i;
        int c = (int)((idx / T) % C);
        float v = fmaxf((agg[idx] - mu)*inv*w[c] + bvec[c], 0.f) + res_t[idx];
        res_t[idx] = v;
        s1 += v; s2 += v*v;
    }
    __shared__ float sh1[256], sh2[256];
    sh1[tid] = s1; sh2[tid] = s2;
    __syncthreads();
    for (int o = 128; o > 0; o >>= 1) {
        if (tid < o) { sh1[tid] += sh1[tid+o]; sh2[tid] += sh2[tid+o]; }
        __syncthreads();
    }
    if (tid == 0) {
        partial[(bg*gridDim.x + blockIdx.x)*2 + 0] = sh1[0];
        partial[(bg*gridDim.x + blockIdx.x)*2 + 1] = sh2[0];
    }
}

// ---------------- fused attention with compacted key columns ----------------
#define SM_Q   (32*68)
#define SM_K   (32*260)
#define SM_S   (68*260)
#define SMEM_FLOATS (SM_Q + SM_K + SM_S)
#define SMEM_BYTES  (SMEM_FLOATS*4)

__global__ void attn_kernel(const float* __restrict__ gq, const float* __restrict__ gkv,
                            const int* __restrict__ sidx, const int* __restrict__ cnt,
                            float* __restrict__ gout) {
    extern __shared__ float sm[];
    float* Qs  = sm;
    float* KVs = Qs + SM_Q;
    float* S   = KVs + SM_K;

    int q = blockIdx.x, g = blockIdx.y, b = blockIdx.z;
    int tid = threadIdx.x;
    long qbase = ((long)(b*HID + g*EDIM)*TQ + q)*TD;
    long kbase = ((long)(b*2*HID + g*EDIM)*TQ + q)*TS;
    long vbase = kbase + (long)HID*TQ*TS;

    int nact  = cnt[b];
    int npad  = (nact + 3) & ~3;
    int ntile = npad >> 2;
    const int* sb = sidx + b*260;

    for (int i = tid; i < SM_Q; i += 256) {
        int e = i/68, d = i%68;
        Qs[i] = (d < TD) ? gq[qbase + (long)e*TQ*TD + d] : 0.f;
    }
    for (int i = tid; i < SM_K; i += 256) {
        int e = i/260, j = i%260;
        KVs[i] = (j < nact) ? gkv[kbase + (long)e*TQ*TS + sb[j]] : 0.f;
    }
    __syncthreads();

    // S[d][j] = sum_e Q[e][d]*K[e][j] over compacted columns
    int ntt = 17*ntile;
    for (int t = tid; t < ntt; t += 256) {
        int dt = t/ntile, st = t%ntile;
        float acc[4][4];
        #pragma unroll
        for (int i = 0; i < 4; i++)
            #pragma unroll
            for (int j = 0; j < 4; j++) acc[i][j] = 0.f;
        #pragma unroll
        for (int e = 0; e < 32; e++) {
            float4 a  = *(const float4*)&Qs[e*68 + dt*4];
            float4 k4 = *(const float4*)&KVs[e*260 + st*4];
            acc[0][0] += a.x*k4.x; acc[0][1] += a.x*k4.y; acc[0][2] += a.x*k4.z; acc[0][3] += a.x*k4.w;
            acc[1][0] += a.y*k4.x; acc[1][1] += a.y*k4.y; acc[1][2] += a.y*k4.z; acc[1][3] += a.y*k4.w;
            acc[2][0] += a.z*k4.x; acc[2][1] += a.z*k4.y; acc[2][2] += a.z*k4.z; acc[2][3] += a.z*k4.w;
            acc[3][0] += a.w*k4.x; acc[3][1] += a.w*k4.y; acc[3][2] += a.w*k4.z; acc[3][3] += a.w*k4.w;
        }
        #pragma unroll
        for (int i = 0; i < 4; i++)
            #pragma unroll
            for (int j = 0; j < 4; j++)
                S[(dt*4 + i)*260 + st*4 + j] = acc[i][j];
    }
    __syncthreads();

    // Load V into the K buffer (compacted), then softmax over the S rows.
    for (int i = tid; i < SM_K; i += 256) {
        int e = i/260, j = i%260;
        KVs[i] = (j < nact) ? gkv[vbase + (long)e*TQ*TS + sb[j]] : 0.f;
    }

    int wid = tid >> 5, lane = tid & 31;
    for (int d = wid; d < TD; d += 8) {
        float mx = -1e30f;
        for (int j = lane; j < nact; j += 32) mx = fmaxf(mx, S[d*260 + j]);
        #pragma unroll
        for (int o = 16; o > 0; o >>= 1) mx = fmaxf(mx, __shfl_xor_sync(0xffffffffu, mx, o));
        float sum = 0.f;
        for (int j = lane; j < nact; j += 32) {
            float e = expf(S[d*260 + j] - mx);
            S[d*260 + j] = e;
            sum += e;
        }
        #pragma unroll
        for (int o = 16; o > 0; o >>= 1) sum += __shfl_xor_sync(0xffffffffu, sum, o);
        float inv = 1.0f/sum;
        for (int j = lane; j < nact; j += 32) S[d*260 + j] *= inv;
        if (lane < npad - nact) S[d*260 + nact + lane] = 0.f;
    }
    __syncthreads();

    // O[e][d] = sum_j A[d][j]*V[e][j]
    long obase = qbase;
    for (int t = tid; t < 8*17; t += 256) {
        int et = t/17, dt = t%17;
        float acc[4][4];
        #pragma unroll
        for (int j = 0; j < 4; j++)
            #pragma unroll
            for (int i = 0; i < 4; i++) acc[j][i] = 0.f;
        for (int s4 = 0; s4 < ntile; s4++) {
            float4 a0 = *(const float4*)&S[(dt*4 + 0)*260 + s4*4];
            float4 a1 = *(const float4*)&S[(dt*4 + 1)*260 + s4*4];
            float4 a2 = *(const float4*)&S[(dt*4 + 2)*260 + s4*4];
            float4 a3 = *(const float4*)&S[(dt*4 + 3)*260 + s4*4];
            float4 v0 = *(const float4*)&KVs[(et*4 + 0)*260 + s4*4];
            float4 v1 = *(const float4*)&KVs[(et*4 + 1)*260 + s4*4];
            float4 v2 = *(const float4*)&KVs[(et*4 + 2)*260 + s4*4];
            float4 v3 = *(const float4*)&KVs[(et*4 + 3)*260 + s4*4];
            acc[0][0] += a0.x*v0.x + a0.y*v0.y + a0.z*v0.z + a0.w*v0.w;
            acc[0][1] += a1.x*v0.x + a1.y*v0.y + a1.z*v0.z + a1.w*v0.w;
            acc[0][2] += a2.x*v0.x + a2.y*v0.y + a2.z*v0.z + a2.w*v0.w;
            acc[0][3] += a3.x*v0.x + a3.y*v0.y + a3.z*v0.z + a3.w*v0.w;
            acc[1][0] += a0.x*v1.x + a0.y*v1.y + a0.z*v1.z + a0.w*v1.w;
            acc[1][1] += a1.x*v1.x + a1.y*v1.y + a1.z*v1.z + a1.w*v1.w;
            acc[1][2] += a2.x*v1.x + a2.y*v1.y + a2.z*v1.z + a2.w*v1.w;
            acc[1][3] += a3.x*v1.x + a3.y*v1.y + a3.z*v1.z + a3.w*v1.w;
            acc[2][0] += a0.x*v2.x + a0.y*v2.y + a0.z*v2.z + a0.w*v2.w;
            acc[2][1] += a1.x*v2.x + a1.y*v2.y + a1.z*v2.z + a1.w*v2.w;
            acc[2][2] += a2.x*v2.x + a2.y*v2.y + a2.z*v2.z + a2.w*v2.w;
            acc[2][3] += a3.x*v2.x + a3.y*v2.y + a3.z*v2.z + a3.w*v2.w;
            acc[3][0] += a0.x*v3.x + a0.y*v3.y + a0.z*v3.z + a0.w*v3.w;
            acc[3][1] += a1.x*v3.x + a1.y*v3.y + a1.z*v3.z + a1.w*v3.w;
            acc[3][2] += a2.x*v3.x + a2.y*v3.y + a2.z*v3.z + a2.w*v3.w;
            acc[3][3] += a3.x*v3.x + a3.y*v3.y + a3.z*v3.z + a3.w*v3.w;
        }
        #pragma unroll
        for (int j = 0; j < 4; j++)
            #pragma unroll
            for (int i = 0; i < 4; i++) {
                int d = dt*4 + i;
                if (d < TD)
                    gout[obase + (long)(et*4 + j)*TQ*TD + d] = acc[j][i];
            }
    }
}

// ---------------- host orchestration ----------------
static void run_gn(const float* x, const float* y, float* out,
                   const float* w, const float* bvec,
                   float* partial, float* stats,
                   int C, int T, int doRelu) {
    long groupSize = (long)(C/4)*T;
    long n = (long)BB*C*T;
    float invN = 1.0f/(float)groupSize;
    gn_reduce<<<dim3(128, 16), 256>>>(x, y, partial, groupSize);
    gn_finalize<<<1, 16>>>(partial, stats, 128, invN);
    gn_apply<<<(unsigned)((n + 255)/256), 256>>>(x, y, out, w, bvec, stats, groupSize, T, C, n, doRelu);
}

extern "C" void kernel_launch(void* const* d_in, const int* in_sizes, int n_in,
                              void* d_out, int out_size) {
    const float* corr   = (const float*)d_in[0];
    const int*   smask  = (const int*)  d_in[1];
    const float* W_sc   = (const float*)d_in[2];
    const float* gnscw  = (const float*)d_in[3];
    const float* gnscb  = (const float*)d_in[4];
    const float* W_qkv  = (const float*)d_in[5];
    const float* b_qkv  = (const float*)d_in[6];
    const float* gn1w   = (const float*)d_in[7];
    const float* gn1b   = (const float*)d_in[8];
    const float* W_agg  = (const float*)d_in[9];
    const float* gn2w   = (const float*)d_in[10];
    const float* gn2b   = (const float*)d_in[11];
    const float* gnow   = (const float*)d_in[12];
    const float* gnob   = (const float*)d_in[13];
    float* out = (float*)d_out;

    float *pooled, *kv, *q, *res, *att, *agg, *partial, *stats;
    int *sidx, *cnt;
    cudaGetSymbolAddress((void**)&pooled, g_pooled);
    cudaGetSymbolAddress((void**)&kv,     g_kv);
    cudaGetSymbolAddress((void**)&q,      g_q);
    cudaGetSymbolAddress((void**)&res,    g_res);
    cudaGetSymbolAddress((void**)&att,    g_att);
    cudaGetSymbolAddress((void**)&agg,    g_agg);
    cudaGetSymbolAddress((void**)&sidx,   g_sidx);
    cudaGetSymbolAddress((void**)&cnt,    g_cnt);
    cudaGetSymbolAddress((void**)&partial,g_partial);
    cudaGetSymbolAddress((void**)&stats,  g_stats);

    const int NPOOL = TQ*TD;     // 16640 = 130*128
    const int NFULL = TQ*TS;     // 65792 = 514*128

    // 1. pooled corr + compacted mask indices
    pool_kernel2<<<BB*CIN*TQ/8, 256>>>(corr, pooled);
    mask_compact<<<BB, 256>>>(smask, sidx, cnt);

    // 2. GEMMs (tensor cores)
    gemm_mma<<<dim3(NPOOL/128, HID/128,   BB), 256>>>(W_qkv,           b_qkv,       pooled, q,   HID,   NPOOL, CIN);
    gemm_mma<<<dim3(NPOOL/128, COUT/128,  BB), 256>>>(W_sc,            nullptr,     pooled, res, COUT,  NPOOL, CIN);
    gemm_mma<<<dim3(NFULL/128, 2*HID/128, BB), 256>>>(W_qkv + HID*CIN, b_qkv + HID, corr,   kv,  2*HID, NFULL, CIN);

    // 3. residual = relu(gn_sc(res))
    run_gn(res, nullptr, res, gnscw, gnscb, partial, stats, COUT, NPOOL, 1);

    // 4. attention (compacted keys)
    cudaFuncSetAttribute(attn_kernel, cudaFuncAttributeMaxDynamicSharedMemorySize, SMEM_BYTES);
    attn_kernel<<<dim3(TQ, NHEAD, BB), 256, SMEM_BYTES>>>(q, kv, sidx, cnt, att);

    // 5. out = relu(gn1(att))
    run_gn(att, nullptr, att, gn1w, gn1b, partial, stats, HID, NPOOL, 1);

    // 6. agg = W_agg @ att
    gemm_mma<<<dim3(NPOOL/128, COUT/128, BB), 256>>>(W_agg, nullptr, att, agg, COUT, NPOOL, HID);

    // 7+8 fused: gn2 stats; t = relu(gn2(agg)) + res (into res) with gn_out reduction; gn_out apply
    {
        long groupSize = (long)(COUT/4)*NPOOL;
        long n = (long)BB*COUT*NPOOL;
        float invN = 1.0f/(float)groupSize;
        gn_reduce<<<dim3(128, 16), 256>>>(agg, nullptr, partial, groupSize);
        gn_finalize<<<1, 16>>>(partial, stats, 128, invN);
        gn_fuse<<<dim3(128, 16), 256>>>(agg, res, gn2w, gn2b, stats, partial, groupSize, NPOOL, COUT);
        gn_finalize<<<1, 16>>>(partial, stats, 128, invN);
        gn_apply<<<(unsigned)((n + 255)/256), 256>>>(res, nullptr, out, gnow, gnob, stats, groupSize, NPOOL, COUT, n, 0);
    }
}

// round 5
// speedup vs baseline: 2.4294x; 1.1181x over previous
#include <cuda_runtime.h>
#include <cuda_bf16.h>
#include <math.h>

#define BB 4
#define CIN 128
#define TQ 256
#define TS 257
#define TD 65
#define HID 256
#define COUT 512
#define NHEAD 8
#define EDIM 32

// ---------------- scratch (static device globals; no allocation) ----------------
__device__ float g_pooled[BB*CIN*TQ*TD];
__device__ float g_corrc[BB*CIN*TQ*260];       // compacted corr columns (packed, dyn stride)
__device__ float g_kv[BB*2*HID*TQ*260];        // compacted K/V (packed, dyn stride)
__device__ float g_q[BB*HID*TQ*TD];
__device__ float g_res[BB*COUT*TQ*TD];
__device__ float g_att[BB*HID*TQ*TD];
__device__ float g_agg[BB*COUT*TQ*TD];
__device__ int   g_sidx[BB*260];
__device__ int   g_cnt[BB];
__device__ float g_partial[16*128*2];
__device__ float g_stats[16*2];
__device__ float g_stats_sc[16*2];
__device__ float g_stats2[16*2];

// ---------------- mask: exact bilinear subsample + active-column compaction ----------------
__global__ void mask_compact(const int* __restrict__ s, int* __restrict__ sidx, int* __restrict__ cnt) {
    int b = blockIdx.x;
    int tid = threadIdx.x;
    int i = tid >> 4, j = tid & 15;
    int act = (s[b*65536 + (i*17)*256 + j*17] > 0) ? 1 : 0;
    __shared__ int sh[256];
    sh[tid] = act;
    __syncthreads();
    for (int off = 1; off < 256; off <<= 1) {
        int v = (tid >= off) ? sh[tid - off] : 0;
        __syncthreads();
        sh[tid] += v;
        __syncthreads();
    }
    if (act) sidx[b*260 + sh[tid]] = tid + 1;    // 1-based s position
    if (tid == 255) cnt[b] = sh[255] + 1;
    if (tid == 0) sidx[b*260] = 0;               // cls always active
}

// ---------------- cst_pool + corr column compaction (one pass over corr) ----------------
__global__ void pool_compact(const float* __restrict__ in, float* __restrict__ out,
                             float* __restrict__ outc,
                             const int* __restrict__ sidx, const int* __restrict__ cnt) {
    __shared__ float row[8][260];
    int wid = threadIdx.x >> 5, lane = threadIdx.x & 31;
    long r = (long)blockIdx.x*8 + wid;           // (b*CIN + c)*TQ + q
    int b  = (int)(r / (CIN*TQ));
    int cq = (int)(r % (CIN*TQ));
    const float* src = in + r*TS;
    for (int i = lane; i < TS; i += 32) row[wid][i] = src[i];
    __syncwarp();
    // pooled output
    float* dst = out + r*TD;
    if (lane == 0) dst[0] = row[wid][0];
    #pragma unroll
    for (int t = lane; t < 64; t += 32) {
        int i = t >> 3, j = t & 7;
        const float* p = &row[wid][1 + i*32 + j*2];
        dst[1 + t] = 0.25f*(p[0] + p[1] + p[16] + p[17]);
    }
    // compacted columns
    int nact = cnt[b];
    int npad4 = (nact + 3) & ~3;
    const int* sb = sidx + b*260;
    int c = cq / TQ, q = cq % TQ;
    float* dc = outc + (long)b*CIN*TQ*260 + (long)c*TQ*npad4 + (long)q*npad4;
    for (int j = lane; j < npad4; j += 32)
        dc[j] = (j < nact) ? row[wid][sb[j]] : 0.f;
}

// ---------------- bf16 split helpers ----------------
__device__ __forceinline__ unsigned pk2(float x, float y) {
    __nv_bfloat162 t = __floats2bfloat162_rn(x, y);
    return *(unsigned*)&t;
}
__device__ __forceinline__ float bflo(float x) {
    __nv_bfloat16 h = __float2bfloat16(x);
    return x - __bfloat162float(h);
}

#define LDMX4(r0,r1,r2,r3,addr) \
    asm volatile("ldmatrix.sync.aligned.m8n8.x4.shared.b16 {%0,%1,%2,%3}, [%4];" \
        : "=r"(r0),"=r"(r1),"=r"(r2),"=r"(r3) : "r"(addr))
#define LDMX2T(r0,r1,addr) \
    asm volatile("ldmatrix.sync.aligned.m8n8.x2.trans.shared.b16 {%0,%1}, [%2];" \
        : "=r"(r0),"=r"(r1) : "r"(addr))
#define MMA16816(c0,c1,c2,c3,a0,a1,a2,a3,b0,b1) \
    asm volatile("mma.sync.aligned.m16n8k16.row.col.f32.bf16.bf16.f32 " \
        "{%0,%1,%2,%3}, {%4,%5,%6,%7}, {%8,%9}, {%0,%1,%2,%3};" \
        : "+f"(c0),"+f"(c1),"+f"(c2),"+f"(c3) \
        : "r"(a0),"r"(a1),"r"(a2),"r"(a3),"r"(b0),"r"(b1))

// ---------------- tensor-core GEMM body (3-term bf16 split) ----------------
#define STRA 24
#define STRX 136
#define ABUF (128*STRA)
#define XBUF (16*STRX)
#define BUFSZ (2*ABUF + 2*XBUF)

// Core computation shared by both GEMM entry points.
__device__ __forceinline__ void gemm_body(
    const float* __restrict__ W, const float* __restrict__ bias,
    const float* __restrict__ Xb, float* __restrict__ Yb,
    int m0, int n0, int N, int K, unsigned short* sm_) {

    int tid = threadIdx.x;
    int wid = tid >> 5, lane = tid & 31;
    int warp_m = wid & 1, warp_n = wid >> 1;

    int arow = tid >> 1, aq = tid & 1;
    const float* Ap = W + (long)(m0 + arow)*K + aq*8;
    int xk = tid >> 4, xn = (tid & 15)*4;
    const float* Xp = Xb + (long)xk*N + n0 + xn;

    int a_mrow = (lane & 7) + ((lane >> 3) & 1)*8;
    int a_koff = ((lane >> 4) & 1)*8;
    int b_krow = lane & 15;

    float acc[4][4][4];
    #pragma unroll
    for (int i = 0; i < 4; i++)
        #pragma unroll
        for (int j = 0; j < 4; j++)
            #pragma unroll
            for (int r = 0; r < 4; r++) acc[i][j][r] = 0.f;

    int nt_chunks = K >> 4;
    {
        float4 a0 = *(const float4*)Ap;
        float4 a1 = *(const float4*)(Ap + 4);
        float4 x0 = *(const float4*)Xp;
        float4 x1 = *(const float4*)(Xp + 64);
        unsigned short* Ah = sm_;
        unsigned short* Al = Ah + ABUF;
        unsigned short* Xh = Ah + 2*ABUF;
        unsigned short* Xl = Xh + XBUF;
        *(uint2*)&Ah[arow*STRA + aq*8]     = make_uint2(pk2(a0.x,a0.y), pk2(a0.z,a0.w));
        *(uint2*)&Ah[arow*STRA + aq*8 + 4] = make_uint2(pk2(a1.x,a1.y), pk2(a1.z,a1.w));
        *(uint2*)&Al[arow*STRA + aq*8]     = make_uint2(pk2(bflo(a0.x),bflo(a0.y)), pk2(bflo(a0.z),bflo(a0.w)));
        *(uint2*)&Al[arow*STRA + aq*8 + 4] = make_uint2(pk2(bflo(a1.x),bflo(a1.y)), pk2(bflo(a1.z),bflo(a1.w)));
        *(uint2*)&Xh[xk*STRX + xn]      = make_uint2(pk2(x0.x,x0.y), pk2(x0.z,x0.w));
        *(uint2*)&Xh[xk*STRX + xn + 64] = make_uint2(pk2(x1.x,x1.y), pk2(x1.z,x1.w));
        *(uint2*)&Xl[xk*STRX + xn]      = make_uint2(pk2(bflo(x0.x),bflo(x0.y)), pk2(bflo(x0.z),bflo(x0.w)));
        *(uint2*)&Xl[xk*STRX + xn + 64] = make_uint2(pk2(bflo(x1.x),bflo(x1.y)), pk2(bflo(x1.z),bflo(x1.w)));
    }
    __syncthreads();

    for (int t = 0; t < nt_chunks; t++) {
        int cur = t & 1;
        float4 a0, a1, x0, x1;
        if (t + 1 < nt_chunks) {
            a0 = *(const float4*)(Ap + (t+1)*16);
            a1 = *(const float4*)(Ap + (t+1)*16 + 4);
            x0 = *(const float4*)(Xp + (long)(t+1)*16*N);
            x1 = *(const float4*)(Xp + (long)(t+1)*16*N + 64);
        }

        const unsigned short* Ah = sm_ + cur*BUFSZ;
        const unsigned short* Al = Ah + ABUF;
        const unsigned short* Xh = Ah + 2*ABUF;
        const unsigned short* Xl = Xh + XBUF;

        unsigned bh[4][2], bl[4][2];
        #pragma unroll
        for (int nt = 0; nt < 4; nt++) {
            int col = warp_n*32 + nt*8;
            unsigned ad = (unsigned)__cvta_generic_to_shared(&Xh[b_krow*STRX + col]);
            LDMX2T(bh[nt][0], bh[nt][1], ad);
            ad = (unsigned)__cvta_generic_to_shared(&Xl[b_krow*STRX + col]);
            LDMX2T(bl[nt][0], bl[nt][1], ad);
        }

        #pragma unroll
        for (int mt = 0; mt < 4; mt++) {
            int row = warp_m*64 + mt*16 + a_mrow;
            unsigned ah0,ah1,ah2,ah3, al0,al1,al2,al3;
            unsigned ad = (unsigned)__cvta_generic_to_shared(&Ah[row*STRA + a_koff]);
            LDMX4(ah0,ah1,ah2,ah3, ad);
            ad = (unsigned)__cvta_generic_to_shared(&Al[row*STRA + a_koff]);
            LDMX4(al0,al1,al2,al3, ad);
            #pragma unroll
            for (int nt = 0; nt < 4; nt++) {
                float* c = acc[mt][nt];
                MMA16816(c[0],c[1],c[2],c[3], ah0,ah1,ah2,ah3, bh[nt][0],bh[nt][1]);
                MMA16816(c[0],c[1],c[2],c[3], ah0,ah1,ah2,ah3, bl[nt][0],bl[nt][1]);
                MMA16816(c[0],c[1],c[2],c[3], al0,al1,al2,al3, bh[nt][0],bh[nt][1]);
            }
        }

        if (t + 1 < nt_chunks) {
            int nxt = cur ^ 1;
            unsigned short* Ah2 = sm_ + nxt*BUFSZ;
            unsigned short* Al2 = Ah2 + ABUF;
            unsigned short* Xh2 = Ah2 + 2*ABUF;
            unsigned short* Xl2 = Xh2 + XBUF;
            *(uint2*)&Ah2[arow*STRA + aq*8]     = make_uint2(pk2(a0.x,a0.y), pk2(a0.z,a0.w));
            *(uint2*)&Ah2[arow*STRA + aq*8 + 4] = make_uint2(pk2(a1.x,a1.y), pk2(a1.z,a1.w));
            *(uint2*)&Al2[arow*STRA + aq*8]     = make_uint2(pk2(bflo(a0.x),bflo(a0.y)), pk2(bflo(a0.z),bflo(a0.w)));
            *(uint2*)&Al2[arow*STRA + aq*8 + 4] = make_uint2(pk2(bflo(a1.x),bflo(a1.y)), pk2(bflo(a1.z),bflo(a1.w)));
            *(uint2*)&Xh2[xk*STRX + xn]      = make_uint2(pk2(x0.x,x0.y), pk2(x0.z,x0.w));
            *(uint2*)&Xh2[xk*STRX + xn + 64] = make_uint2(pk2(x1.x,x1.y), pk2(x1.z,x1.w));
            *(uint2*)&Xl2[xk*STRX + xn]      = make_uint2(pk2(bflo(x0.x),bflo(x0.y)), pk2(bflo(x0.z),bflo(x0.w)));
            *(uint2*)&Xl2[xk*STRX + xn + 64] = make_uint2(pk2(bflo(x1.x),bflo(x1.y)), pk2(bflo(x1.z),bflo(x1.w)));
            __syncthreads();
        }
    }

    int g = lane >> 2, tq = lane & 3;
    #pragma unroll
    for (int mt = 0; mt < 4; mt++) {
        int r0 = m0 + warp_m*64 + mt*16 + g;
        float b0v = bias ? bias[r0]   : 0.f;
        float b1v = bias ? bias[r0+8] : 0.f;
        #pragma unroll
        for (int nt = 0; nt < 4; nt++) {
            int c = n0 + warp_n*32 + nt*8 + tq*2;
            float* a = acc[mt][nt];
            *(float2*)&Yb[(long)r0*N + c]     = make_float2(a[0]+b0v, a[1]+b0v);
            *(float2*)&Yb[(long)(r0+8)*N + c] = make_float2(a[2]+b1v, a[3]+b1v);
        }
    }
}

// static-N GEMM: Y[b] = W @ X[b] (+bias)
__global__ void __launch_bounds__(256, 2)
gemm_mma(const float* __restrict__ W, const float* __restrict__ bias,
         const float* __restrict__ X, float* __restrict__ Y,
         int M, int N, int K) {
    __shared__ __align__(16) unsigned short sm_[2*BUFSZ];
    int b = blockIdx.z;
    gemm_body(W, bias, X + (long)b*K*N, Y + (long)b*M*N,
              blockIdx.y*128, blockIdx.x*128, N, K, sm_);
}

// dynamic-N GEMM over compacted columns (KV). X/Y use fixed max batch stride, packed rows.
__global__ void __launch_bounds__(256, 2)
gemm_mma_dyn(const float* __restrict__ W, const float* __restrict__ bias,
             const float* __restrict__ X, float* __restrict__ Y,
             int K, const int* __restrict__ cnt) {
    __shared__ __align__(16) unsigned short sm_[2*BUFSZ];
    int b = blockIdx.z;
    int nact = cnt[b];
    int npad4 = (nact + 3) & ~3;
    int N = TQ*npad4;                 // always a multiple of 128
    int n0 = blockIdx.x*128;
    if (n0 >= N) return;
    gemm_body(W, bias, X + (long)b*CIN*TQ*260, Y + (long)b*2*HID*TQ*260,
              blockIdx.y*128, n0, N, K, sm_);
}

// ---------------- GroupNorm kernels ----------------
__global__ void gn_reduce(const float* __restrict__ x, const float* __restrict__ y,
                          float* __restrict__ partial, long groupSize) {
    long bg = blockIdx.y;
    long base = bg*groupSize;
    int tid = threadIdx.x;
    float s1 = 0.f, s2 = 0.f;
    for (long i = (long)blockIdx.x*blockDim.x + tid; i < groupSize; i += (long)gridDim.x*blockDim.x) {
        float v = x[base + i];
        if (y) v += y[base + i];
        s1 += v; s2 += v*v;
    }
    __shared__ float sh1[256], sh2[256];
    sh1[tid] = s1; sh2[tid] = s2;
    __syncthreads();
    for (int o = 128; o > 0; o >>= 1) {
        if (tid < o) { sh1[tid] += sh1[tid+o]; sh2[tid] += sh2[tid+o]; }
        __syncthreads();
    }
    if (tid == 0) {
        partial[(bg*gridDim.x + blockIdx.x)*2 + 0] = sh1[0];
        partial[(bg*gridDim.x + blockIdx.x)*2 + 1] = sh2[0];
    }
}

__global__ void gn_finalize(const float* __restrict__ partial, float* __restrict__ stats,
                            int nb, float invN) {
    int bg = threadIdx.x;
    if (bg >= 16) return;
    float s1 = 0.f, s2 = 0.f;
    for (int i = 0; i < nb; i++) {
        s1 += partial[(bg*nb + i)*2 + 0];
        s2 += partial[(bg*nb + i)*2 + 1];
    }
    float mean = s1*invN;
    float var  = fmaxf(s2*invN - mean*mean, 0.f);
    stats[bg*2 + 0] = mean;
    stats[bg*2 + 1] = 1.0f/sqrtf(var + 1e-5f);
}

__global__ void gn_apply(const float* __restrict__ x, const float* __restrict__ y,
                         float* __restrict__ out,
                         const float* __restrict__ w, const float* __restrict__ bvec,
                         const float* __restrict__ stats,
                         long groupSize, int T, int C, long n, int doRelu) {
    long idx = (long)blockIdx.x*blockDim.x + threadIdx.x;
    if (idx >= n) return;
    int bg = (int)(idx / groupSize);
    int c  = (int)((idx / T) % C);
    float v = x[idx];
    if (y) v += y[idx];
    v = (v - stats[bg*2])*stats[bg*2 + 1]*w[c] + bvec[c];
    if (doRelu) v = fmaxf(v, 0.f);
    out[idx] = v;
}

// Fused: t = relu(gn2(agg)) + relu(gn_sc(res_raw)), written over res, plus sums of t.
__global__ void gn_fuse2(const float* __restrict__ agg, float* __restrict__ res_t,
                         const float* __restrict__ w2, const float* __restrict__ b2,
                         const float* __restrict__ wsc, const float* __restrict__ bsc,
                         const float* __restrict__ stats2, const float* __restrict__ statssc,
                         float* __restrict__ partial,
                         long groupSize, int T, int C) {
    long bg = blockIdx.y;
    long base = bg*groupSize;
    float mu2 = stats2[bg*2],  inv2 = stats2[bg*2 + 1];
    float mus = statssc[bg*2], invs = statssc[bg*2 + 1];
    int tid = threadIdx.x;
    float s1 = 0.f, s2 = 0.f;
    for (long i = (long)blockIdx.x*blockDim.x + tid; i < groupSize; i += (long)gridDim.x*blockDim.x) {
        long idx = base + i;
        int c = (int)((idx / T) % C);
        float a = fmaxf((agg[idx]  - mu2)*inv2*w2[c]  + b2[c],  0.f);
        float r = fmaxf((res_t[idx] - mus)*invs*wsc[c] + bsc[c], 0.f);
        float v = a + r;
        res_t[idx] = v;
        s1 += v; s2 += v*v;
    }
    __shared__ float sh1[256], sh2[256];
    sh1[tid] = s1; sh2[tid] = s2;
    __syncthreads();
    for (int o = 128; o > 0; o >>= 1) {
        if (tid < o) { sh1[tid] += sh1[tid+o]; sh2[tid] += sh2[tid+o]; }
        __syncthreads();
    }
    if (tid == 0) {
        partial[(bg*gridDim.x + blockIdx.x)*2 + 0] = sh1[0];
        partial[(bg*gridDim.x + blockIdx.x)*2 + 1] = sh2[0];
    }
}

// ---------------- fused attention over compacted (packed) K/V ----------------
#define SM_Q   (32*68)
#define SM_K   (32*260)
#define SM_S   (68*260)
#define SMEM_FLOATS (SM_Q + SM_K + SM_S)
#define SMEM_BYTES  (SMEM_FLOATS*4)

__global__ void attn_kernel(const float* __restrict__ gq, const float* __restrict__ gkv,
                            const int* __restrict__ cnt, float* __restrict__ gout) {
    extern __shared__ float sm[];
    float* Qs  = sm;
    float* KVs = Qs + SM_Q;
    float* S   = KVs + SM_K;

    int q = blockIdx.x, g = blockIdx.y, b = blockIdx.z;
    int tid = threadIdx.x;
    long qbase = ((long)(b*HID + g*EDIM)*TQ + q)*TD;

    int nact  = cnt[b];
    int npad  = (nact + 3) & ~3;
    int ntile = npad >> 2;
    long kvs  = (long)TQ*npad;                              // packed channel-row stride
    const float* kptr = gkv + (long)b*2*HID*TQ*260 + (long)(g*EDIM)*kvs + (long)q*npad;
    const float* vptr = kptr + (long)HID*kvs;

    for (int i = tid; i < SM_Q; i += 256) {
        int e = i/68, d = i%68;
        Qs[i] = (d < TD) ? gq[qbase + (long)e*TQ*TD + d] : 0.f;
    }
    for (int i = tid; i < SM_K; i += 256) {
        int e = i/260, j = i%260;
        KVs[i] = (j < nact) ? kptr[(long)e*kvs + j] : 0.f;  // coalesced in j
    }
    __syncthreads();

    // S[d][j] = sum_e Q[e][d]*K[e][j]
    int ntt = 17*ntile;
    for (int t = tid; t < ntt; t += 256) {
        int dt = t/ntile, st = t%ntile;
        float acc[4][4];
        #pragma unroll
        for (int i = 0; i < 4; i++)
            #pragma unroll
            for (int j = 0; j < 4; j++) acc[i][j] = 0.f;
        #pragma unroll
        for (int e = 0; e < 32; e++) {
            float4 a  = *(const float4*)&Qs[e*68 + dt*4];
            float4 k4 = *(const float4*)&KVs[e*260 + st*4];
            acc[0][0] += a.x*k4.x; acc[0][1] += a.x*k4.y; acc[0][2] += a.x*k4.z; acc[0][3] += a.x*k4.w;
            acc[1][0] += a.y*k4.x; acc[1][1] += a.y*k4.y; acc[1][2] += a.y*k4.z; acc[1][3] += a.y*k4.w;
            acc[2][0] += a.z*k4.x; acc[2][1] += a.z*k4.y; acc[2][2] += a.z*k4.z; acc[2][3] += a.z*k4.w;
            acc[3][0] += a.w*k4.x; acc[3][1] += a.w*k4.y; acc[3][2] += a.w*k4.z; acc[3][3] += a.w*k4.w;
        }
        #pragma unroll
        for (int i = 0; i < 4; i++)
            #pragma unroll
            for (int j = 0; j < 4; j++)
                S[(dt*4 + i)*260 + st*4 + j] = acc[i][j];
    }
    __syncthreads();

    // Load V (coalesced), then softmax.
    for (int i = tid; i < SM_K; i += 256) {
        int e = i/260, j = i%260;
        KVs[i] = (j < nact) ? vptr[(long)e*kvs + j] : 0.f;
    }

    int wid = tid >> 5, lane = tid & 31;
    for (int d = wid; d < TD; d += 8) {
        float mx = -1e30f;
        for (int j = lane; j < nact; j += 32) mx = fmaxf(mx, S[d*260 + j]);
        #pragma unroll
        for (int o = 16; o > 0; o >>= 1) mx = fmaxf(mx, __shfl_xor_sync(0xffffffffu, mx, o));
        float sum = 0.f;
        for (int j = lane; j < nact; j += 32) {
            float e = expf(S[d*260 + j] - mx);
            S[d*260 + j] = e;
            sum += e;
        }
        #pragma unroll
        for (int o = 16; o > 0; o >>= 1) sum += __shfl_xor_sync(0xffffffffu, sum, o);
        float inv = 1.0f/sum;
        for (int j = lane; j < nact; j += 32) S[d*260 + j] *= inv;
        if (lane < npad - nact) S[d*260 + nact + lane] = 0.f;
    }
    __syncthreads();

    // O[e][d] = sum_j A[d][j]*V[e][j]
    long obase = qbase;
    for (int t = tid; t < 8*17; t += 256) {
        int et = t/17, dt = t%17;
        float acc[4][4];
        #pragma unroll
        for (int j = 0; j < 4; j++)
            #pragma unroll
            for (int i = 0; i < 4; i++) acc[j][i] = 0.f;
        for (int s4 = 0; s4 < ntile; s4++) {
            float4 a0 = *(const float4*)&S[(dt*4 + 0)*260 + s4*4];
            float4 a1 = *(const float4*)&S[(dt*4 + 1)*260 + s4*4];
            float4 a2 = *(const float4*)&S[(dt*4 + 2)*260 + s4*4];
            float4 a3 = *(const float4*)&S[(dt*4 + 3)*260 + s4*4];
            float4 v0 = *(const float4*)&KVs[(et*4 + 0)*260 + s4*4];
            float4 v1 = *(const float4*)&KVs[(et*4 + 1)*260 + s4*4];
            float4 v2 = *(const float4*)&KVs[(et*4 + 2)*260 + s4*4];
            float4 v3 = *(const float4*)&KVs[(et*4 + 3)*260 + s4*4];
            acc[0][0] += a0.x*v0.x + a0.y*v0.y + a0.z*v0.z + a0.w*v0.w;
            acc[0][1] += a1.x*v0.x + a1.y*v0.y + a1.z*v0.z + a1.w*v0.w;
            acc[0][2] += a2.x*v0.x + a2.y*v0.y + a2.z*v0.z + a2.w*v0.w;
            acc[0][3] += a3.x*v0.x + a3.y*v0.y + a3.z*v0.z + a3.w*v0.w;
            acc[1][0] += a0.x*v1.x + a0.y*v1.y + a0.z*v1.z + a0.w*v1.w;
            acc[1][1] += a1.x*v1.x + a1.y*v1.y + a1.z*v1.z + a1.w*v1.w;
            acc[1][2] += a2.x*v1.x + a2.y*v1.y + a2.z*v1.z + a2.w*v1.w;
            acc[1][3] += a3.x*v1.x + a3.y*v1.y + a3.z*v1.z + a3.w*v1.w;
            acc[2][0] += a0.x*v2.x + a0.y*v2.y + a0.z*v2.z + a0.w*v2.w;
            acc[2][1] += a1.x*v2.x + a1.y*v2.y + a1.z*v2.z + a1.w*v2.w;
            acc[2][2] += a2.x*v2.x + a2.y*v2.y + a2.z*v2.z + a2.w*v2.w;
            acc[2][3] += a3.x*v2.x + a3.y*v2.y + a3.z*v2.z + a3.w*v2.w;
            acc[3][0] += a0.x*v3.x + a0.y*v3.y + a0.z*v3.z + a0.w*v3.w;
            acc[3][1] += a1.x*v3.x + a1.y*v3.y + a1.z*v3.z + a1.w*v3.w;
            acc[3][2] += a2.x*v3.x + a2.y*v3.y + a2.z*v3.z + a2.w*v3.w;
            acc[3][3] += a3.x*v3.x + a3.y*v3.y + a3.z*v3.z + a3.w*v3.w;
        }
        #pragma unroll
        for (int j = 0; j < 4; j++)
            #pragma unroll
            for (int i = 0; i < 4; i++) {
                int d = dt*4 + i;
                if (d < TD)
                    gout[obase + (long)(et*4 + j)*TQ*TD + d] = acc[j][i];
            }
    }
}

// ---------------- host orchestration ----------------
static void run_gn(const float* x, const float* y, float* out,
                   const float* w, const float* bvec,
                   float* partial, float* stats,
                   int C, int T, int doRelu) {
    long groupSize = (long)(C/4)*T;
    long n = (long)BB*C*T;
    float invN = 1.0f/(float)groupSize;
    gn_reduce<<<dim3(128, 16), 256>>>(x, y, partial, groupSize);
    gn_finalize<<<1, 16>>>(partial, stats, 128, invN);
    gn_apply<<<(unsigned)((n + 255)/256), 256>>>(x, y, out, w, bvec, stats, groupSize, T, C, n, doRelu);
}

extern "C" void kernel_launch(void* const* d_in, const int* in_sizes, int n_in,
                              void* d_out, int out_size) {
    const float* corr   = (const float*)d_in[0];
    const int*   smask  = (const int*)  d_in[1];
    const float* W_sc   = (const float*)d_in[2];
    const float* gnscw  = (const float*)d_in[3];
    const float* gnscb  = (const float*)d_in[4];
    const float* W_qkv  = (const float*)d_in[5];
    const float* b_qkv  = (const float*)d_in[6];
    const float* gn1w   = (const float*)d_in[7];
    const float* gn1b   = (const float*)d_in[8];
    const float* W_agg  = (const float*)d_in[9];
    const float* gn2w   = (const float*)d_in[10];
    const float* gn2b   = (const float*)d_in[11];
    const float* gnow   = (const float*)d_in[12];
    const float* gnob   = (const float*)d_in[13];
    float* out = (float*)d_out;

    float *pooled, *corrc, *kv, *q, *res, *att, *agg, *partial, *stats, *stats_sc, *stats2;
    int *sidx, *cnt;
    cudaGetSymbolAddress((void**)&pooled,  g_pooled);
    cudaGetSymbolAddress((void**)&corrc,   g_corrc);
    cudaGetSymbolAddress((void**)&kv,      g_kv);
    cudaGetSymbolAddress((void**)&q,       g_q);
    cudaGetSymbolAddress((void**)&res,     g_res);
    cudaGetSymbolAddress((void**)&att,     g_att);
    cudaGetSymbolAddress((void**)&agg,     g_agg);
    cudaGetSymbolAddress((void**)&sidx,    g_sidx);
    cudaGetSymbolAddress((void**)&cnt,     g_cnt);
    cudaGetSymbolAddress((void**)&partial, g_partial);
    cudaGetSymbolAddress((void**)&stats,   g_stats);
    cudaGetSymbolAddress((void**)&stats_sc,g_stats_sc);
    cudaGetSymbolAddress((void**)&stats2,  g_stats2);

    const int NPOOL = TQ*TD;     // 16640 = 130*128
    const int NKVMAX = TQ*260;   // 66560 = 520*128 (worst case)

    // 1. mask compaction first (pool_compact consumes it), then pool+compact corr
    mask_compact<<<BB, 256>>>(smask, sidx, cnt);
    pool_compact<<<BB*CIN*TQ/8, 256>>>(corr, pooled, corrc, sidx, cnt);

    // 2. GEMMs (tensor cores). KV runs on compacted columns with early-exit grid.
    gemm_mma<<<dim3(NPOOL/128, HID/128,  BB), 256>>>(W_qkv, b_qkv,   pooled, q,   HID,  NPOOL, CIN);
    gemm_mma<<<dim3(NPOOL/128, COUT/128, BB), 256>>>(W_sc,  nullptr, pooled, res, COUT, NPOOL, CIN);
    gemm_mma_dyn<<<dim3(NKVMAX/128, 2*HID/128, BB), 256>>>(W_qkv + HID*CIN, b_qkv + HID, corrc, kv, CIN, cnt);

    // 3. gn_sc stats only (apply folded into gn_fuse2); res stays raw
    {
        long groupSize = (long)(COUT/4)*NPOOL;
        gn_reduce<<<dim3(128, 16), 256>>>(res, nullptr, partial, groupSize);
        gn_finalize<<<1, 16>>>(partial, stats_sc, 128, 1.0f/(float)groupSize);
    }

    // 4. attention (packed compacted K/V)
    cudaFuncSetAttribute(attn_kernel, cudaFuncAttributeMaxDynamicSharedMemorySize, SMEM_BYTES);
    attn_kernel<<<dim3(TQ, NHEAD, BB), 256, SMEM_BYTES>>>(q, kv, cnt, att);

    // 5. out = relu(gn1(att))
    run_gn(att, nullptr, att, gn1w, gn1b, partial, stats, HID, NPOOL, 1);

    // 6. agg = W_agg @ att
    gemm_mma<<<dim3(NPOOL/128, COUT/128, BB), 256>>>(W_agg, nullptr, att, agg, COUT, NPOOL, HID);

    // 7+8: gn2 stats; t = relu(gn2(agg)) + relu(gn_sc(res_raw)) with gn_out reduction; gn_out apply
    {
        long groupSize = (long)(COUT/4)*NPOOL;
        long n = (long)BB*COUT*NPOOL;
        float invN = 1.0f/(float)groupSize;
        gn_reduce<<<dim3(128, 16), 256>>>(agg, nullptr, partial, groupSize);
        gn_finalize<<<1, 16>>>(partial, stats2, 128, invN);
        gn_fuse2<<<dim3(128, 16), 256>>>(agg, res, gn2w, gn2b, gnscw, gnscb,
                                         stats2, stats_sc, partial, groupSize, NPOOL, COUT);
        gn_finalize<<<1, 16>>>(partial, stats, 128, invN);
        gn_apply<<<(unsigned)((n + 255)/256), 256>>>(res, nullptr, out, gnow, gnob, stats, groupSize, NPOOL, COUT, n, 0);
    }
}

// round 6
// speedup vs baseline: 2.5645x; 1.0556x over previous
#include <cuda_runtime.h>
#include <cuda_bf16.h>
#include <math.h>

#define BB 4
#define CIN 128
#define TQ 256
#define TS 257
#define TD 65
#define HID 256
#define COUT 512
#define NHEAD 8
#define EDIM 32

// ---------------- scratch (static device globals; no allocation) ----------------
__device__ float g_pooled[BB*CIN*TQ*TD];
__device__ float g_corrc[BB*CIN*TQ*260];
__device__ float g_kv[BB*2*HID*TQ*260];
__device__ float g_q[BB*HID*TQ*TD];
__device__ float g_res[BB*COUT*TQ*TD];
__device__ float g_att[BB*HID*TQ*TD];
__device__ float g_agg[BB*COUT*TQ*TD];
__device__ int   g_sidx[BB*260];
__device__ int   g_cnt[BB];
__device__ float g_partial[16*130*2];      // generic partials (gemm stats: 130/bg, fuse: 128/bg)
__device__ float g_partial1[16*512*2];     // gn1 partials from attention
__device__ float g_stats[16*2];
__device__ float g_stats_sc[16*2];
__device__ float g_stats1[16*2];
__device__ float g_stats2[16*2];

// ---------------- fast exp: FMA-pipe only (no MUFU, no F2I) ----------------
__device__ __forceinline__ float fexp(float x) {
    float y = x * 1.44269504f;
    y = fmaxf(y, -126.0f);
    float z = y + 12582912.0f;                 // round-to-nearest via magic constant
    int   r = __float_as_int(z) - 0x4B400000;  // (int)round(y)
    float f = y - (z - 12582912.0f);           // frac in [-0.5, 0.5]
    float p =        1.53832606e-4f;
    p = fmaf(p, f, 1.33978284e-3f);
    p = fmaf(p, f, 9.61833310e-3f);
    p = fmaf(p, f, 5.55036624e-2f);
    p = fmaf(p, f, 2.40226500e-1f);
    p = fmaf(p, f, 6.93147182e-1f);
    p = fmaf(p, f, 1.0f);
    return p * __int_as_float((r + 127) << 23);
}

// ---------------- mask: exact bilinear subsample + active-column compaction ----------------
__global__ void mask_compact(const int* __restrict__ s, int* __restrict__ sidx, int* __restrict__ cnt) {
    int b = blockIdx.x;
    int tid = threadIdx.x;
    int i = tid >> 4, j = tid & 15;
    int act = (s[b*65536 + (i*17)*256 + j*17] > 0) ? 1 : 0;
    __shared__ int sh[256];
    sh[tid] = act;
    __syncthreads();
    for (int off = 1; off < 256; off <<= 1) {
        int v = (tid >= off) ? sh[tid - off] : 0;
        __syncthreads();
        sh[tid] += v;
        __syncthreads();
    }
    if (act) sidx[b*260 + sh[tid]] = tid + 1;
    if (tid == 255) cnt[b] = sh[255] + 1;
    if (tid == 0) sidx[b*260] = 0;
}

// ---------------- cst_pool + corr column compaction ----------------
__global__ void pool_compact(const float* __restrict__ in, float* __restrict__ out,
                             float* __restrict__ outc,
                             const int* __restrict__ sidx, const int* __restrict__ cnt) {
    __shared__ float row[8][260];
    int wid = threadIdx.x >> 5, lane = threadIdx.x & 31;
    long r = (long)blockIdx.x*8 + wid;
    int b  = (int)(r / (CIN*TQ));
    int cq = (int)(r % (CIN*TQ));
    const float* src = in + r*TS;
    for (int i = lane; i < TS; i += 32) row[wid][i] = src[i];
    __syncwarp();
    float* dst = out + r*TD;
    if (lane == 0) dst[0] = row[wid][0];
    #pragma unroll
    for (int t = lane; t < 64; t += 32) {
        int i = t >> 3, j = t & 7;
        const float* p = &row[wid][1 + i*32 + j*2];
        dst[1 + t] = 0.25f*(p[0] + p[1] + p[16] + p[17]);
    }
    int nact = cnt[b];
    int npad4 = (nact + 3) & ~3;
    const int* sb = sidx + b*260;
    int c = cq / TQ, q = cq % TQ;
    float* dc = outc + (long)b*CIN*TQ*260 + (long)c*TQ*npad4 + (long)q*npad4;
    for (int j = lane; j < npad4; j += 32)
        dc[j] = (j < nact) ? row[wid][sb[j]] : 0.f;
}

// ---------------- bf16 split helpers ----------------
__device__ __forceinline__ unsigned pk2(float x, float y) {
    __nv_bfloat162 t = __floats2bfloat162_rn(x, y);
    return *(unsigned*)&t;
}
__device__ __forceinline__ float bflo(float x) {
    __nv_bfloat16 h = __float2bfloat16(x);
    return x - __bfloat162float(h);
}

#define LDMX4(r0,r1,r2,r3,addr) \
    asm volatile("ldmatrix.sync.aligned.m8n8.x4.shared.b16 {%0,%1,%2,%3}, [%4];" \
        : "=r"(r0),"=r"(r1),"=r"(r2),"=r"(r3) : "r"(addr))
#define LDMX2T(r0,r1,addr) \
    asm volatile("ldmatrix.sync.aligned.m8n8.x2.trans.shared.b16 {%0,%1}, [%2];" \
        : "=r"(r0),"=r"(r1) : "r"(addr))
#define MMA16816(c0,c1,c2,c3,a0,a1,a2,a3,b0,b1) \
    asm volatile("mma.sync.aligned.m16n8k16.row.col.f32.bf16.bf16.f32 " \
        "{%0,%1,%2,%3}, {%4,%5,%6,%7}, {%8,%9}, {%0,%1,%2,%3};" \
        : "+f"(c0),"+f"(c1),"+f"(c2),"+f"(c3) \
        : "r"(a0),"r"(a1),"r"(a2),"r"(a3),"r"(b0),"r"(b1))

// ---------------- tensor-core GEMM body (3-term bf16 split) ----------------
#define STRA 24
#define STRX 136
#define ABUF (128*STRA)
#define XBUF (16*STRX)
#define BUFSZ (2*ABUF + 2*XBUF)

// optional per-row affine+relu transform of X (groupnorm apply fused into loader)
__device__ __forceinline__ float4 xform4(float4 v, int k, const float* stats,
                                         const float* w, const float* bv) {
    float mu = stats[(k>>6)*2], iv = stats[(k>>6)*2 + 1];
    float ww = w[k]*iv;
    float of = fmaf(-mu, ww, bv[k]);
    v.x = fmaxf(fmaf(v.x, ww, of), 0.f);
    v.y = fmaxf(fmaf(v.y, ww, of), 0.f);
    v.z = fmaxf(fmaf(v.z, ww, of), 0.f);
    v.w = fmaxf(fmaf(v.w, ww, of), 0.f);
    return v;
}

template<bool XF, bool STATS>
__device__ __forceinline__ void gemm_body(
    const float* __restrict__ W, const float* __restrict__ bias,
    const float* __restrict__ Xb, float* __restrict__ Yb,
    int m0, int n0, int N, int K, unsigned short* sm_,
    const float* xfStats, const float* xfW, const float* xfB,
    float* partial, int pIdx) {

    int tid = threadIdx.x;
    int wid = tid >> 5, lane = tid & 31;
    int warp_m = wid & 1, warp_n = wid >> 1;

    int arow = tid >> 1, aq = tid & 1;
    const float* Ap = W + (long)(m0 + arow)*K + aq*8;
    int xk = tid >> 4, xn = (tid & 15)*4;
    const float* Xp = Xb + (long)xk*N + n0 + xn;

    int a_mrow = (lane & 7) + ((lane >> 3) & 1)*8;
    int a_koff = ((lane >> 4) & 1)*8;
    int b_krow = lane & 15;

    float acc[4][4][4];
    #pragma unroll
    for (int i = 0; i < 4; i++)
        #pragma unroll
        for (int j = 0; j < 4; j++)
            #pragma unroll
            for (int r = 0; r < 4; r++) acc[i][j][r] = 0.f;

    int nt_chunks = K >> 4;
    {
        float4 a0 = *(const float4*)Ap;
        float4 a1 = *(const float4*)(Ap + 4);
        float4 x0 = *(const float4*)Xp;
        float4 x1 = *(const float4*)(Xp + 64);
        if (XF) { x0 = xform4(x0, xk, xfStats, xfW, xfB); x1 = xform4(x1, xk, xfStats, xfW, xfB); }
        unsigned short* Ah = sm_;
        unsigned short* Al = Ah + ABUF;
        unsigned short* Xh = Ah + 2*ABUF;
        unsigned short* Xl = Xh + XBUF;
        *(uint2*)&Ah[arow*STRA + aq*8]     = make_uint2(pk2(a0.x,a0.y), pk2(a0.z,a0.w));
        *(uint2*)&Ah[arow*STRA + aq*8 + 4] = make_uint2(pk2(a1.x,a1.y), pk2(a1.z,a1.w));
        *(uint2*)&Al[arow*STRA + aq*8]     = make_uint2(pk2(bflo(a0.x),bflo(a0.y)), pk2(bflo(a0.z),bflo(a0.w)));
        *(uint2*)&Al[arow*STRA + aq*8 + 4] = make_uint2(pk2(bflo(a1.x),bflo(a1.y)), pk2(bflo(a1.z),bflo(a1.w)));
        *(uint2*)&Xh[xk*STRX + xn]      = make_uint2(pk2(x0.x,x0.y), pk2(x0.z,x0.w));
        *(uint2*)&Xh[xk*STRX + xn + 64] = make_uint2(pk2(x1.x,x1.y), pk2(x1.z,x1.w));
        *(uint2*)&Xl[xk*STRX + xn]      = make_uint2(pk2(bflo(x0.x),bflo(x0.y)), pk2(bflo(x0.z),bflo(x0.w)));
        *(uint2*)&Xl[xk*STRX + xn + 64] = make_uint2(pk2(bflo(x1.x),bflo(x1.y)), pk2(bflo(x1.z),bflo(x1.w)));
    }
    __syncthreads();

    for (int t = 0; t < nt_chunks; t++) {
        int cur = t & 1;
        float4 a0, a1, x0, x1;
        if (t + 1 < nt_chunks) {
            a0 = *(const float4*)(Ap + (t+1)*16);
            a1 = *(const float4*)(Ap + (t+1)*16 + 4);
            x0 = *(const float4*)(Xp + (long)(t+1)*16*N);
            x1 = *(const float4*)(Xp + (long)(t+1)*16*N + 64);
            if (XF) {
                int k = (t+1)*16 + xk;
                x0 = xform4(x0, k, xfStats, xfW, xfB);
                x1 = xform4(x1, k, xfStats, xfW, xfB);
            }
        }

        const unsigned short* Ah = sm_ + cur*BUFSZ;
        const unsigned short* Al = Ah + ABUF;
        const unsigned short* Xh = Ah + 2*ABUF;
        const unsigned short* Xl = Xh + XBUF;

        unsigned bh[4][2], bl[4][2];
        #pragma unroll
        for (int nt = 0; nt < 4; nt++) {
            int col = warp_n*32 + nt*8;
            unsigned ad = (unsigned)__cvta_generic_to_shared(&Xh[b_krow*STRX + col]);
            LDMX2T(bh[nt][0], bh[nt][1], ad);
            ad = (unsigned)__cvta_generic_to_shared(&Xl[b_krow*STRX + col]);
            LDMX2T(bl[nt][0], bl[nt][1], ad);
        }

        #pragma unroll
        for (int mt = 0; mt < 4; mt++) {
            int row = warp_m*64 + mt*16 + a_mrow;
            unsigned ah0,ah1,ah2,ah3, al0,al1,al2,al3;
            unsigned ad = (unsigned)__cvta_generic_to_shared(&Ah[row*STRA + a_koff]);
            LDMX4(ah0,ah1,ah2,ah3, ad);
            ad = (unsigned)__cvta_generic_to_shared(&Al[row*STRA + a_koff]);
            LDMX4(al0,al1,al2,al3, ad);
            #pragma unroll
            for (int nt = 0; nt < 4; nt++) {
                float* c = acc[mt][nt];
                MMA16816(c[0],c[1],c[2],c[3], ah0,ah1,ah2,ah3, bh[nt][0],bh[nt][1]);
                MMA16816(c[0],c[1],c[2],c[3], ah0,ah1,ah2,ah3, bl[nt][0],bl[nt][1]);
                MMA16816(c[0],c[1],c[2],c[3], al0,al1,al2,al3, bh[nt][0],bh[nt][1]);
            }
        }

        if (t + 1 < nt_chunks) {
            int nxt = cur ^ 1;
            unsigned short* Ah2 = sm_ + nxt*BUFSZ;
            unsigned short* Al2 = Ah2 + ABUF;
            unsigned short* Xh2 = Ah2 + 2*ABUF;
            unsigned short* Xl2 = Xh2 + XBUF;
            *(uint2*)&Ah2[arow*STRA + aq*8]     = make_uint2(pk2(a0.x,a0.y), pk2(a0.z,a0.w));
            *(uint2*)&Ah2[arow*STRA + aq*8 + 4] = make_uint2(pk2(a1.x,a1.y), pk2(a1.z,a1.w));
            *(uint2*)&Al2[arow*STRA + aq*8]     = make_uint2(pk2(bflo(a0.x),bflo(a0.y)), pk2(bflo(a0.z),bflo(a0.w)));
            *(uint2*)&Al2[arow*STRA + aq*8 + 4] = make_uint2(pk2(bflo(a1.x),bflo(a1.y)), pk2(bflo(a1.z),bflo(a1.w)));
            *(uint2*)&Xh2[xk*STRX + xn]      = make_uint2(pk2(x0.x,x0.y), pk2(x0.z,x0.w));
            *(uint2*)&Xh2[xk*STRX + xn + 64] = make_uint2(pk2(x1.x,x1.y), pk2(x1.z,x1.w));
            *(uint2*)&Xl2[xk*STRX + xn]      = make_uint2(pk2(bflo(x0.x),bflo(x0.y)), pk2(bflo(x0.z),bflo(x0.w)));
            *(uint2*)&Xl2[xk*STRX + xn + 64] = make_uint2(pk2(bflo(x1.x),bflo(x1.y)), pk2(bflo(x1.z),bflo(x1.w)));
            __syncthreads();
        }
    }

    int g = lane >> 2, tq = lane & 3;
    float s1 = 0.f, s2 = 0.f;
    #pragma unroll
    for (int mt = 0; mt < 4; mt++) {
        int r0 = m0 + warp_m*64 + mt*16 + g;
        float b0v = bias ? bias[r0]   : 0.f;
        float b1v = bias ? bias[r0+8] : 0.f;
        #pragma unroll
        for (int nt = 0; nt < 4; nt++) {
            int c = n0 + warp_n*32 + nt*8 + tq*2;
            float* a = acc[mt][nt];
            float v0 = a[0]+b0v, v1 = a[1]+b0v, v2 = a[2]+b1v, v3 = a[3]+b1v;
            *(float2*)&Yb[(long)r0*N + c]     = make_float2(v0, v1);
            *(float2*)&Yb[(long)(r0+8)*N + c] = make_float2(v2, v3);
            if (STATS) {
                s1 += v0 + v1 + v2 + v3;
                s2 += v0*v0 + v1*v1 + v2*v2 + v3*v3;
            }
        }
    }
    if (STATS) {
        __syncthreads();
        float* red = (float*)sm_;
        red[tid] = s1; red[tid + 256] = s2;
        __syncthreads();
        for (int o = 128; o > 0; o >>= 1) {
            if (tid < o) { red[tid] += red[tid+o]; red[tid+256] += red[tid+256+o]; }
            __syncthreads();
        }
        if (tid == 0) {
            partial[pIdx*2 + 0] = red[0];
            partial[pIdx*2 + 1] = red[256];
        }
    }
}

template<bool XF, bool STATS>
__global__ void __launch_bounds__(256, 2)
gemm_tc(const float* __restrict__ W, const float* __restrict__ bias,
        const float* __restrict__ X, float* __restrict__ Y,
        int M, int N, int K,
        const float* __restrict__ xfStats, const float* __restrict__ xfW,
        const float* __restrict__ xfB, float* __restrict__ partial) {
    __shared__ __align__(16) unsigned short sm_[2*BUFSZ];
    int b = blockIdx.z;
    int pIdx = (b*gridDim.y + blockIdx.y)*gridDim.x + blockIdx.x;
    gemm_body<XF, STATS>(W, bias, X + (long)b*K*N, Y + (long)b*M*N,
                         blockIdx.y*128, blockIdx.x*128, N, K, sm_,
                         XF ? xfStats + b*8 : nullptr, xfW, xfB, partial, pIdx);
}

__global__ void __launch_bounds__(256, 2)
gemm_tc_dyn(const float* __restrict__ W, const float* __restrict__ bias,
            const float* __restrict__ X, float* __restrict__ Y,
            int K, const int* __restrict__ cnt) {
    __shared__ __align__(16) unsigned short sm_[2*BUFSZ];
    int b = blockIdx.z;
    int nact = cnt[b];
    int npad4 = (nact + 3) & ~3;
    int N = TQ*npad4;
    int n0 = blockIdx.x*128;
    if (n0 >= N) return;
    gemm_body<false,false>(W, bias, X + (long)b*CIN*TQ*260, Y + (long)b*2*HID*TQ*260,
                           blockIdx.y*128, n0, N, K, sm_, nullptr, nullptr, nullptr, nullptr, 0);
}

// ---------------- GroupNorm kernels ----------------
__global__ void gn_finalize(const float* __restrict__ partial, float* __restrict__ stats,
                            int nb, float invN) {
    int bg = threadIdx.x;
    if (bg >= 16) return;
    float s1 = 0.f, s2 = 0.f;
    for (int i = 0; i < nb; i++) {
        s1 += partial[(bg*nb + i)*2 + 0];
        s2 += partial[(bg*nb + i)*2 + 1];
    }
    float mean = s1*invN;
    float var  = fmaxf(s2*invN - mean*mean, 0.f);
    stats[bg*2 + 0] = mean;
    stats[bg*2 + 1] = 1.0f/sqrtf(var + 1e-5f);
}

__global__ void gn_apply(const float* __restrict__ x, float* __restrict__ out,
                         const float* __restrict__ w, const float* __restrict__ bvec,
                         const float* __restrict__ stats,
                         long groupSize, int T, int C, long n) {
    long idx = (long)blockIdx.x*blockDim.x + threadIdx.x;
    if (idx >= n) return;
    int bg = (int)(idx / groupSize);
    int c  = (int)((idx / T) % C);
    float v = (x[idx] - stats[bg*2])*stats[bg*2 + 1]*w[c] + bvec[c];
    out[idx] = v;
}

// t = relu(gn2(agg)) + relu(gn_sc(res_raw)) into res, plus sums of t for gn_out.
__global__ void gn_fuse2(const float* __restrict__ agg, float* __restrict__ res_t,
                         const float* __restrict__ w2, const float* __restrict__ b2,
                         const float* __restrict__ wsc, const float* __restrict__ bsc,
                         const float* __restrict__ stats2, const float* __restrict__ statssc,
                         float* __restrict__ partial,
                         long groupSize, int T, int C) {
    long bg = blockIdx.y;
    long base = bg*groupSize;
    float mu2 = stats2[bg*2],  inv2 = stats2[bg*2 + 1];
    float mus = statssc[bg*2], invs = statssc[bg*2 + 1];
    int tid = threadIdx.x;
    float s1 = 0.f, s2 = 0.f;
    for (long i = (long)blockIdx.x*blockDim.x + tid; i < groupSize; i += (long)gridDim.x*blockDim.x) {
        long idx = base + i;
        int c = (int)((idx / T) % C);
        float a = fmaxf((agg[idx]   - mu2)*inv2*w2[c]  + b2[c],  0.f);
        float r = fmaxf((res_t[idx] - mus)*invs*wsc[c] + bsc[c], 0.f);
        float v = a + r;
        res_t[idx] = v;
        s1 += v; s2 += v*v;
    }
    __shared__ float sh1[256], sh2[256];
    sh1[tid] = s1; sh2[tid] = s2;
    __syncthreads();
    for (int o = 128; o > 0; o >>= 1) {
        if (tid < o) { sh1[tid] += sh1[tid+o]; sh2[tid] += sh2[tid+o]; }
        __syncthreads();
    }
    if (tid == 0) {
        partial[(bg*gridDim.x + blockIdx.x)*2 + 0] = sh1[0];
        partial[(bg*gridDim.x + blockIdx.x)*2 + 1] = sh2[0];
    }
}

// ---------------- fused attention over compacted K/V; emits gn1 partials ----------------
#define SM_Q   (32*68)
#define SM_K   (32*260)
#define SM_S   (68*260)
#define SMEM_FLOATS (SM_Q + SM_K + SM_S)
#define SMEM_BYTES  (SMEM_FLOATS*4)

__global__ void attn_kernel(const float* __restrict__ gq, const float* __restrict__ gkv,
                            const int* __restrict__ cnt, float* __restrict__ gout,
                            float* __restrict__ partial1) {
    extern __shared__ float sm[];
    float* Qs  = sm;
    float* KVs = Qs + SM_Q;
    float* S   = KVs + SM_K;
    __shared__ float Sinv[68];
    __shared__ float red1[256], red2[256];

    int q = blockIdx.x, g = blockIdx.y, b = blockIdx.z;
    int tid = threadIdx.x;
    long qbase = ((long)(b*HID + g*EDIM)*TQ + q)*TD;

    int nact  = cnt[b];
    int npad  = (nact + 3) & ~3;
    int ntile = npad >> 2;
    long kvs  = (long)TQ*npad;
    const float* kptr = gkv + (long)b*2*HID*TQ*260 + (long)(g*EDIM)*kvs + (long)q*npad;
    const float* vptr = kptr + (long)HID*kvs;

    for (int i = tid; i < SM_Q; i += 256) {
        int e = i/68, d = i%68;
        Qs[i] = (d < TD) ? gq[qbase + (long)e*TQ*TD + d] : 0.f;
    }
    for (int i = tid; i < SM_K; i += 256) {
        int e = i/260, j = i%260;
        KVs[i] = (j < nact) ? kptr[(long)e*kvs + j] : 0.f;
    }
    __syncthreads();

    // S[d][j] = sum_e Q[e][d]*K[e][j]
    int ntt = 17*ntile;
    for (int t = tid; t < ntt; t += 256) {
        int dt = t/ntile, st = t%ntile;
        float acc[4][4];
        #pragma unroll
        for (int i = 0; i < 4; i++)
            #pragma unroll
            for (int j = 0; j < 4; j++) acc[i][j] = 0.f;
        #pragma unroll
        for (int e = 0; e < 32; e++) {
            float4 a  = *(const float4*)&Qs[e*68 + dt*4];
            float4 k4 = *(const float4*)&KVs[e*260 + st*4];
            acc[0][0] += a.x*k4.x; acc[0][1] += a.x*k4.y; acc[0][2] += a.x*k4.z; acc[0][3] += a.x*k4.w;
            acc[1][0] += a.y*k4.x; acc[1][1] += a.y*k4.y; acc[1][2] += a.y*k4.z; acc[1][3] += a.y*k4.w;
            acc[2][0] += a.z*k4.x; acc[2][1] += a.z*k4.y; acc[2][2] += a.z*k4.z; acc[2][3] += a.z*k4.w;
            acc[3][0] += a.w*k4.x; acc[3][1] += a.w*k4.y; acc[3][2] += a.w*k4.z; acc[3][3] += a.w*k4.w;
        }
        #pragma unroll
        for (int i = 0; i < 4; i++)
            #pragma unroll
            for (int j = 0; j < 4; j++)
                S[(dt*4 + i)*260 + st*4 + j] = acc[i][j];
    }
    __syncthreads();

    // Load V (coalesced) while softmax (exp only; normalization deferred to O-phase)
    for (int i = tid; i < SM_K; i += 256) {
        int e = i/260, j = i%260;
        KVs[i] = (j < nact) ? vptr[(long)e*kvs + j] : 0.f;
    }

    int wid = tid >> 5, lane = tid & 31;
    for (int d = wid; d < TD; d += 8) {
        float mx = -1e30f;
        for (int j = lane; j < nact; j += 32) mx = fmaxf(mx, S[d*260 + j]);
        #pragma unroll
        for (int o = 16; o > 0; o >>= 1) mx = fmaxf(mx, __shfl_xor_sync(0xffffffffu, mx, o));
        float sum = 0.f;
        for (int j = lane; j < nact; j += 32) {
            float e = fexp(S[d*260 + j] - mx);
            S[d*260 + j] = e;
            sum += e;
        }
        #pragma unroll
        for (int o = 16; o > 0; o >>= 1) sum += __shfl_xor_sync(0xffffffffu, sum, o);
        if (lane == 0) Sinv[d] = 1.0f/sum;
        // pad cols of S hold raw scores but V pad cols are 0 -> no contribution
        if (lane < npad - nact) S[d*260 + nact + lane] = 0.f;
    }
    __syncthreads();

    // O[e][d] = Sinv[d] * sum_j E[d][j]*V[e][j]; emit gn1 sums of outputs
    long obase = qbase;
    float s1 = 0.f, s2 = 0.f;
    for (int t = tid; t < 8*17; t += 256) {
        int et = t/17, dt = t%17;
        float acc[4][4];
        #pragma unroll
        for (int j = 0; j < 4; j++)
            #pragma unroll
            for (int i = 0; i < 4; i++) acc[j][i] = 0.f;
        for (int s4 = 0; s4 < ntile; s4++) {
            float4 a0 = *(const float4*)&S[(dt*4 + 0)*260 + s4*4];
            float4 a1 = *(const float4*)&S[(dt*4 + 1)*260 + s4*4];
            float4 a2 = *(const float4*)&S[(dt*4 + 2)*260 + s4*4];
            float4 a3 = *(const float4*)&S[(dt*4 + 3)*260 + s4*4];
            float4 v0 = *(const float4*)&KVs[(et*4 + 0)*260 + s4*4];
            float4 v1 = *(const float4*)&KVs[(et*4 + 1)*260 + s4*4];
            float4 v2 = *(const float4*)&KVs[(et*4 + 2)*260 + s4*4];
            float4 v3 = *(const float4*)&KVs[(et*4 + 3)*260 + s4*4];
            acc[0][0] += a0.x*v0.x + a0.y*v0.y + a0.z*v0.z + a0.w*v0.w;
            acc[0][1] += a1.x*v0.x + a1.y*v0.y + a1.z*v0.z + a1.w*v0.w;
            acc[0][2] += a2.x*v0.x + a2.y*v0.y + a2.z*v0.z + a2.w*v0.w;
            acc[0][3] += a3.x*v0.x + a3.y*v0.y + a3.z*v0.z + a3.w*v0.w;
            acc[1][0] += a0.x*v1.x + a0.y*v1.y + a0.z*v1.z + a0.w*v1.w;
            acc[1][1] += a1.x*v1.x + a1.y*v1.y + a1.z*v1.z + a1.w*v1.w;
            acc[1][2] += a2.x*v1.x + a2.y*v1.y + a2.z*v1.z + a2.w*v1.w;
            acc[1][3] += a3.x*v1.x + a3.y*v1.y + a3.z*v1.z + a3.w*v1.w;
            acc[2][0] += a0.x*v2.x + a0.y*v2.y + a0.z*v2.z + a0.w*v2.w;
            acc[2][1] += a1.x*v2.x + a1.y*v2.y + a1.z*v2.z + a1.w*v2.w;
            acc[2][2] += a2.x*v2.x + a2.y*v2.y + a2.z*v2.z + a2.w*v2.w;
            acc[2][3] += a3.x*v2.x + a3.y*v2.y + a3.z*v2.z + a3.w*v2.w;
            acc[3][0] += a0.x*v3.x + a0.y*v3.y + a0.z*v3.z + a0.w*v3.w;
            acc[3][1] += a1.x*v3.x + a1.y*v3.y + a1.z*v3.z + a1.w*v3.w;
            acc[3][2] += a2.x*v3.x + a2.y*v3.y + a2.z*v3.z + a2.w*v3.w;
            acc[3][3] += a3.x*v3.x + a3.y*v3.y + a3.z*v3.z + a3.w*v3.w;
        }
        #pragma unroll
        for (int j = 0; j < 4; j++)
            #pragma unroll
            for (int i = 0; i < 4; i++) {
                int d = dt*4 + i;
                if (d < TD) {
                    float v = acc[j][i]*Sinv[d];
                    gout[obase + (long)(et*4 + j)*TQ*TD + d] = v;
                    s1 += v; s2 += v*v;
                }
            }
    }

    // block reduce gn1 partials
    red1[tid] = s1; red2[tid] = s2;
    __syncthreads();
    for (int o = 128; o > 0; o >>= 1) {
        if (tid < o) { red1[tid] += red1[tid+o]; red2[tid] += red2[tid+o]; }
        __syncthreads();
    }
    if (tid == 0) {
        int pIdx = (b*4 + (g >> 1))*512 + (g & 1)*256 + q;
        partial1[pIdx*2 + 0] = red1[0];
        partial1[pIdx*2 + 1] = red2[0];
    }
}

// ---------------- host orchestration ----------------
extern "C" void kernel_launch(void* const* d_in, const int* in_sizes, int n_in,
                              void* d_out, int out_size) {
    const float* corr   = (const float*)d_in[0];
    const int*   smask  = (const int*)  d_in[1];
    const float* W_sc   = (const float*)d_in[2];
    const float* gnscw  = (const float*)d_in[3];
    const float* gnscb  = (const float*)d_in[4];
    const float* W_qkv  = (const float*)d_in[5];
    const float* b_qkv  = (const float*)d_in[6];
    const float* gn1w   = (const float*)d_in[7];
    const float* gn1b   = (const float*)d_in[8];
    const float* W_agg  = (const float*)d_in[9];
    const float* gn2w   = (const float*)d_in[10];
    const float* gn2b   = (const float*)d_in[11];
    const float* gnow   = (const float*)d_in[12];
    const float* gnob   = (const float*)d_in[13];
    float* out = (float*)d_out;

    float *pooled, *corrc, *kv, *q, *res, *att, *agg;
    float *partial, *partial1, *stats, *stats_sc, *stats1, *stats2;
    int *sidx, *cnt;
    cudaGetSymbolAddress((void**)&pooled,  g_pooled);
    cudaGetSymbolAddress((void**)&corrc,   g_corrc);
    cudaGetSymbolAddress((void**)&kv,      g_kv);
    cudaGetSymbolAddress((void**)&q,       g_q);
    cudaGetSymbolAddress((void**)&res,     g_res);
    cudaGetSymbolAddress((void**)&att,     g_att);
    cudaGetSymbolAddress((void**)&agg,     g_agg);
    cudaGetSymbolAddress((void**)&sidx,    g_sidx);
    cudaGetSymbolAddress((void**)&cnt,     g_cnt);
    cudaGetSymbolAddress((void**)&partial, g_partial);
    cudaGetSymbolAddress((void**)&partial1,g_partial1);
    cudaGetSymbolAddress((void**)&stats,   g_stats);
    cudaGetSymbolAddress((void**)&stats_sc,g_stats_sc);
    cudaGetSymbolAddress((void**)&stats1,  g_stats1);
    cudaGetSymbolAddress((void**)&stats2,  g_stats2);

    const int NPOOL = TQ*TD;     // 16640 = 130*128
    const int NKVMAX = TQ*260;   // 66560 = 520*128

    const long gsC = (long)(COUT/4)*NPOOL;      // COUT group size
    const long gsH = (long)(HID/4)*NPOOL;       // HID group size
    const float invC = 1.0f/(float)gsC;
    const float invH = 1.0f/(float)gsH;

    // 1. mask compaction, then pool + compact corr
    mask_compact<<<BB, 256>>>(smask, sidx, cnt);
    pool_compact<<<BB*CIN*TQ/8, 256>>>(corr, pooled, corrc, sidx, cnt);

    // 2. GEMMs. res emits gn_sc partials; kv over compacted columns.
    gemm_tc<false,false><<<dim3(NPOOL/128, HID/128,  BB), 256>>>(W_qkv, b_qkv,   pooled, q,   HID,  NPOOL, CIN, nullptr, nullptr, nullptr, nullptr);
    gemm_tc<false,true ><<<dim3(NPOOL/128, COUT/128, BB), 256>>>(W_sc,  nullptr, pooled, res, COUT, NPOOL, CIN, nullptr, nullptr, nullptr, partial);
    gemm_tc_dyn<<<dim3(NKVMAX/128, 2*HID/128, BB), 256>>>(W_qkv + HID*CIN, b_qkv + HID, corrc, kv, CIN, cnt);
    gn_finalize<<<1, 16>>>(partial, stats_sc, 130, invC);

    // 3. attention (emits gn1 partials)
    cudaFuncSetAttribute(attn_kernel, cudaFuncAttributeMaxDynamicSharedMemorySize, SMEM_BYTES);
    attn_kernel<<<dim3(TQ, NHEAD, BB), 256, SMEM_BYTES>>>(q, kv, cnt, att, partial1);
    gn_finalize<<<1, 16>>>(partial1, stats1, 512, invH);

    // 4. agg = W_agg @ relu(gn1(att)) — gn1 applied in loader; emits gn2 partials
    gemm_tc<true,true><<<dim3(NPOOL/128, COUT/128, BB), 256>>>(W_agg, nullptr, att, agg, COUT, NPOOL, HID, stats1, gn1w, gn1b, partial);
    gn_finalize<<<1, 16>>>(partial, stats2, 130, invC);

    // 5. t = relu(gn2(agg)) + relu(gn_sc(res)) with gn_out reduction; then gn_out apply
    gn_fuse2<<<dim3(128, 16), 256>>>(agg, res, gn2w, gn2b, gnscw, gnscb,
                                     stats2, stats_sc, partial, gsC, NPOOL, COUT);
    gn_finalize<<<1, 16>>>(partial, stats, 128, invC);
    {
        long n = (long)BB*COUT*NPOOL;
        gn_apply<<<(unsigned)((n + 255)/256), 256>>>(res, out, gnow, gnob, stats, gsC, NPOOL, COUT, n);
    }
}